// round 13
// baseline (speedup 1.0000x reference)
#include <cuda_runtime.h>
#include <cuda_bf16.h>
#include <cstdint>

using bf16 = __nv_bfloat16;

// ---------------- problem dims ----------------
#define BB   2
#define SS   1024
#define DD   1024
#define HH   16
#define DFFN 4096
#define LLAY 2
#define VV   32000
#define MM   (BB*SS)

// ---------------- ternary weight buffer (int8, EXACT codes) ----------------
#define OQKV 0L
#define OO   (OQKV + (long)LLAY*3*DD*DD)
#define OGU  (OO   + (long)LLAY*DD*DD)
#define ODW  (OGU  + (long)LLAY*2*DFFN*DD)
#define OHD  (ODW  + (long)LLAY*DD*DFFN)
#define WTOT (OHD  + (long)VV*DD)

__device__ int8_t g_w8[WTOT];         // ternary codes as int8 (exact)
__device__ float  g_sc[WTOT/128];     // weight scales, transposed per tensor: [g][N]
__device__ int    g_wtype;

// ---------------- activation scratch ----------------
__device__ float  g_x[MM*DD];
__device__ float  g_h[MM*DD];
__device__ float  g_qkv[(size_t)MM*3*DD];
__device__ float  g_gu[(size_t)MM*2*DFFN];
__device__ float  g_o[MM*DD];
__device__ int8_t g_qh[(size_t)MM*DFFN], g_ql[(size_t)MM*DFFN];
__device__ float  g_sah[32*MM], g_sal[32*MM];   // activation scales, [g][M]

// ---------------- dtype probe ----------------
__global__ void probe_kernel(const void* raw) {
    if (threadIdx.x != 0) return;
    const unsigned* pw = (const unsigned*)raw;
    bool is_i32 = true;
    for (int i = 0; i < 256; i++) {
        unsigned w = pw[i];
        if (!(w == 0u || w == 1u || w == 0xFFFFFFFFu)) { is_i32 = false; break; }
    }
    if (is_i32) { g_wtype = 1; return; }
    bool is_f32 = true;
    for (int i = 0; i < 256; i++) {
        unsigned w = pw[i];
        if (!(w == 0u || w == 0x3F800000u || w == 0xBF800000u)) { is_f32 = false; break; }
    }
    if (is_f32) { g_wtype = 2; return; }
    const unsigned short* ph = (const unsigned short*)raw;
    bool is_b16 = true;
    for (int i = 0; i < 512; i++) {
        unsigned short w = ph[i];
        if (!(w == 0u || w == 0x3F80u || w == 0xBF80u)) { is_b16 = false; break; }
    }
    g_wtype = is_b16 ? 3 : 0;
}

__device__ __forceinline__ float load_tern(const void* p, long i, int t) {
    if (t == 1) return (float)((const int*)p)[i];
    if (t == 2) return ((const float*)p)[i];
    if (t == 3) return __bfloat162float(((const bf16*)p)[i]);
    return (float)((const int8_t*)p)[i];
}

// ---------------- weight convert: exact -> int8 ----------------
__global__ void convert_t8(const void* __restrict__ src, long srcOff, long dstOff, long n) {
    int t = g_wtype;
    if (t == 1) {
        long stride = (long)gridDim.x * blockDim.x * 4;
        for (long i = ((long)blockIdx.x * blockDim.x + threadIdx.x) * 4; i < n; i += stride) {
            int4 a = *(const int4*)((const int*)src + srcOff + i);
            char4 o = make_char4((char)a.x, (char)a.y, (char)a.z, (char)a.w);
            *(char4*)(g_w8 + dstOff + i) = o;
        }
    } else {
        long stride = (long)gridDim.x * blockDim.x;
        for (long i = (long)blockIdx.x * blockDim.x + threadIdx.x; i < n; i += stride)
            g_w8[dstOff + i] = (int8_t)(int)load_tern(src, srcOff + i, t);
    }
}

// ---------------- weight scale transpose: src [N][Kg] -> g_sc[dstOff + g*strideN + colOff + n] ----------------
__global__ void transp_sc(const float* __restrict__ src, long srcOff, long dstOff,
                          int N, int Kg, int strideN, int colOff) {
    long total = (long)N * Kg;
    long stride = (long)gridDim.x * blockDim.x;
    for (long i = (long)blockIdx.x * blockDim.x + threadIdx.x; i < total; i += stride) {
        int n = (int)(i / Kg), g = (int)(i % Kg);
        g_sc[dstOff + (long)g * strideN + colOff + n] = src[srcOff + i];
    }
}

// ---------------- embedding ----------------
__global__ void embed_kernel(const int* __restrict__ ids, const void* __restrict__ et,
                             const float* __restrict__ es, float* __restrict__ x) {
    int t = g_wtype;
    int m = blockIdx.x;
    long base = (long)ids[m] * DD;
    for (int d = threadIdx.x; d < DD; d += blockDim.x) {
        long idx = base + d;
        x[(long)m * DD + d] = load_tern(et, idx, t) * es[idx >> 7];
    }
}

// ---------------- quantization core: one warp handles one 128-group ----------------
__device__ __forceinline__ float wmax32(float v) {
    #pragma unroll
    for (int o = 16; o; o >>= 1) v = fmaxf(v, __shfl_xor_sync(0xffffffffu, v, o));
    return v;
}

__device__ __forceinline__ void quant_group(float4 y, long elemIdx, long gIdx,
                                            int8_t* qh, int8_t* ql, float* sh, float* sl, int lane) {
    float gm = fmaxf(fmaxf(fabsf(y.x), fabsf(y.y)), fmaxf(fabsf(y.z), fabsf(y.w)));
    gm = wmax32(gm);
    float s1  = (gm > 0.f) ? gm * (1.f / 127.f) : 1.f;
    float inv1 = (gm > 0.f) ? 127.f / gm : 0.f;
    int q0 = __float2int_rn(y.x * inv1), q1 = __float2int_rn(y.y * inv1);
    int q2 = __float2int_rn(y.z * inv1), q3 = __float2int_rn(y.w * inv1);
    *(char4*)(qh + elemIdx) = make_char4((char)q0, (char)q1, (char)q2, (char)q3);
    float r0 = fmaf(-(float)q0, s1, y.x), r1 = fmaf(-(float)q1, s1, y.y);
    float r2 = fmaf(-(float)q2, s1, y.z), r3 = fmaf(-(float)q3, s1, y.w);
    float rm = fmaxf(fmaxf(fabsf(r0), fabsf(r1)), fmaxf(fabsf(r2), fabsf(r3)));
    rm = wmax32(rm);
    float s2  = (rm > 0.f) ? rm * (1.f / 127.f) : 0.f;
    float inv2 = (rm > 0.f) ? 127.f / rm : 0.f;
    int p0 = __float2int_rn(r0 * inv2), p1 = __float2int_rn(r1 * inv2);
    int p2 = __float2int_rn(r2 * inv2), p3 = __float2int_rn(r3 * inv2);
    *(char4*)(ql + elemIdx) = make_char4((char)p0, (char)p1, (char)p2, (char)p3);
    if (lane == 0) { sh[gIdx] = s1; sl[gIdx] = s2; }
}

// ---------------- rmsnorm + fused 2-level int8 quant (K=1024) ----------------
__global__ __launch_bounds__(256)
void rmsnorm_q(const float* __restrict__ x, const float* __restrict__ w, float* __restrict__ hout,
               int8_t* __restrict__ qh, int8_t* __restrict__ ql,
               float* __restrict__ sh, float* __restrict__ sl) {
    int m = blockIdx.x, tid = threadIdx.x;
    int wp = tid >> 5, lane = tid & 31;
    int col = wp * 128 + lane * 4;
    float4 a = *(const float4*)(x + (long)m * DD + col);
    float ss = a.x * a.x + a.y * a.y + a.z * a.z + a.w * a.w;
    __shared__ float red[256];
    red[tid] = ss; __syncthreads();
    #pragma unroll
    for (int st = 128; st > 0; st >>= 1) {
        if (tid < st) red[tid] += red[tid + st];
        __syncthreads();
    }
    float r = rsqrtf(red[0] * (1.0f / DD) + 1e-6f);
    float4 ww = *(const float4*)(w + col);
    float4 y = make_float4(a.x * r * ww.x, a.y * r * ww.y, a.z * r * ww.z, a.w * r * ww.w);
    if (hout) *(float4*)(hout + (long)m * DD + col) = y;
    quant_group(y, (long)m * DD + col, (long)wp * MM + m, qh, ql, sh, sl, lane);
}

// ---------------- standalone quant for attention output (K=1024) ----------------
__global__ __launch_bounds__(256)
void quant_act(const float* __restrict__ A, int8_t* __restrict__ qh, int8_t* __restrict__ ql,
               float* __restrict__ sh, float* __restrict__ sl) {
    int m = blockIdx.x, tid = threadIdx.x;
    int wp = tid >> 5, lane = tid & 31;
    int col = wp * 128 + lane * 4;
    float4 y = *(const float4*)(A + (long)m * DD + col);
    quant_group(y, (long)m * DD + col, (long)wp * MM + m, qh, ql, sh, sl, lane);
}

// ---------------- silu(g)*u + fused quant (K=4096) ----------------
__global__ __launch_bounds__(256)
void silumul_q(const float* __restrict__ gu, int8_t* __restrict__ qh, int8_t* __restrict__ ql,
               float* __restrict__ sh, float* __restrict__ sl) {
    int m = blockIdx.y, cx = blockIdx.x, tid = threadIdx.x;
    int wp = tid >> 5, lane = tid & 31;
    int col = cx * 1024 + wp * 128 + lane * 4;      // within DFFN
    float4 gg = *(const float4*)(gu + (size_t)m * (2 * DFFN) + col);
    float4 uu = *(const float4*)(gu + (size_t)m * (2 * DFFN) + DFFN + col);
    float4 y;
    y.x = gg.x / (1.f + expf(-gg.x)) * uu.x;
    y.y = gg.y / (1.f + expf(-gg.y)) * uu.y;
    y.z = gg.z / (1.f + expf(-gg.z)) * uu.z;
    y.w = gg.w / (1.f + expf(-gg.w)) * uu.w;
    quant_group(y, (size_t)m * DFFN + col, (long)(cx * 8 + wp) * MM + m, qh, ql, sh, sl, lane);
}

// ---------------- mma helpers ----------------
__device__ __forceinline__ void cpa16(uint32_t d, const void* s) {
    asm volatile("cp.async.ca.shared.global [%0], [%1], 16;\n" :: "r"(d), "l"(s));
}
__device__ __forceinline__ void ldsm4(uint32_t* r, uint32_t a) {
    asm volatile("ldmatrix.sync.aligned.m8n8.x4.shared.b16 {%0,%1,%2,%3},[%4];"
                 : "=r"(r[0]), "=r"(r[1]), "=r"(r[2]), "=r"(r[3]) : "r"(a));
}
__device__ __forceinline__ void imma16832(int* c, const uint32_t* a, const uint32_t* b) {
    asm volatile("mma.sync.aligned.m16n8k32.row.col.s32.s8.s8.s32 "
                 "{%0,%1,%2,%3},{%4,%5,%6,%7},{%8,%9},{%0,%1,%2,%3};"
                 : "+r"(c[0]), "+r"(c[1]), "+r"(c[2]), "+r"(c[3])
                 : "r"(a[0]), "r"(a[1]), "r"(a[2]), "r"(a[3]), "r"(b[0]), "r"(b[1]));
}

// ---------------- 2-product int8 group-scaled GEMM ----------------
// C[M,N] (+)= sum_g sw[g][n] * ( sah[g][m]*sum_{k in g} qh*T + sal[g][m]*sum ql*T )
// BM=128, BN=64, BK=32, 512 threads (16 warps as 4x4, warp tile 32x16), 4-stage cp.async.
// smem stage: Ah(128x48B) + Al(128x48B) + T(64x48B) = 15360 B.
#define STGI  15360
#define GSMI  (4*STGI)

template<bool ACCF>
__global__ __launch_bounds__(512, 1)
void gemm2i(const int8_t* __restrict__ Ah, const int8_t* __restrict__ Al,
            const float* __restrict__ sAh, const float* __restrict__ sAl,
            const int8_t* __restrict__ T,  const float* __restrict__ sW,
            float* __restrict__ C, int M, int N, int K) {
    extern __shared__ char smem_raw[];
    const uint32_t sbase = (uint32_t)__cvta_generic_to_shared(smem_raw);
    const int tid = threadIdx.x, lane = tid & 31, wid = tid >> 5;
    const int wm = wid >> 2, wn = wid & 3;
    const int bm = blockIdx.y * 128, bn = blockIdx.x * 64;

    int aoffB[2], colv[2], rowv[4];
    {
        #pragma unroll
        for (int mi = 0; mi < 2; mi++)
            aoffB[mi] = (wm * 32 + mi * 16 + (lane & 15)) * 48 + (lane >> 4) * 16;
        #pragma unroll
        for (int ni = 0; ni < 2; ni++) colv[ni] = bn + wn * 16 + ni * 8 + (lane & 3) * 2;
        #pragma unroll
        for (int rr = 0; rr < 4; rr++) rowv[rr] = bm + wm * 32 + rr * 8 + (lane >> 2);
    }
    const int boffB = (wn * 16 + ((lane >> 4) & 1) * 8 + (lane & 7)) * 48 + ((lane >> 3) & 1) * 16;

    float accM[2][2][4];
    int accPh[2][2][4], accPl[2][2][4];
    #pragma unroll
    for (int i = 0; i < 2; i++)
        #pragma unroll
        for (int j = 0; j < 2; j++)
            #pragma unroll
            for (int c = 0; c < 4; c++) { accM[i][j][c] = 0.f; accPh[i][j][c] = 0; accPl[i][j][c] = 0; }

    auto load_stage = [&](int kt) {
        uint32_t sb = sbase + (kt & 3) * STGI;
        {
            int ch = tid & 255, r = ch >> 1, hf = ch & 1;
            const int8_t* src = ((tid < 256) ? Ah : Al) + (size_t)(bm + r) * K + (size_t)kt * 32 + hf * 16;
            cpa16(sb + ((tid < 256) ? 0 : 6144) + r * 48 + hf * 16, src);
        }
        if (tid < 128) {
            int r = tid >> 1, hf = tid & 1;
            cpa16(sb + 12288 + r * 48 + hf * 16,
                  T + (size_t)(bn + r) * K + (size_t)kt * 32 + hf * 16);
        }
    };

    const int KT = K >> 5;
    load_stage(0); asm volatile("cp.async.commit_group;\n" ::: "memory");
    load_stage(1); asm volatile("cp.async.commit_group;\n" ::: "memory");
    load_stage(2); asm volatile("cp.async.commit_group;\n" ::: "memory");

    float2 swv[2];
    float  sah4[4], sal4[4];

    for (int kt = 0; kt < KT; kt++) {
        if ((kt & 3) == 0) {     // prefetch this group's scales (used at fold, 3 kt later)
            int g = kt >> 2;
            #pragma unroll
            for (int ni = 0; ni < 2; ni++)
                swv[ni] = __ldg((const float2*)(sW + (size_t)g * N + colv[ni]));
            #pragma unroll
            for (int rr = 0; rr < 4; rr++) {
                sah4[rr] = __ldg(sAh + (size_t)g * M + rowv[rr]);
                sal4[rr] = __ldg(sAl + (size_t)g * M + rowv[rr]);
            }
        }

        asm volatile("cp.async.wait_group 2;\n" ::: "memory");
        __syncthreads();
        if (kt + 3 < KT) load_stage(kt + 3);
        asm volatile("cp.async.commit_group;\n" ::: "memory");

        uint32_t sb = sbase + (kt & 3) * STGI;
        uint32_t b4[4], a4[2][4];
        ldsm4(b4, sb + 12288 + boffB);
        #pragma unroll
        for (int mi = 0; mi < 2; mi++) ldsm4(a4[mi], sb + aoffB[mi]);
        #pragma unroll
        for (int mi = 0; mi < 2; mi++)
            #pragma unroll
            for (int ni = 0; ni < 2; ni++) imma16832(accPh[mi][ni], a4[mi], &b4[ni * 2]);
        #pragma unroll
        for (int mi = 0; mi < 2; mi++) ldsm4(a4[mi], sb + 6144 + aoffB[mi]);
        #pragma unroll
        for (int mi = 0; mi < 2; mi++)
            #pragma unroll
            for (int ni = 0; ni < 2; ni++) imma16832(accPl[mi][ni], a4[mi], &b4[ni * 2]);

        if ((kt & 3) == 3) {     // fold group partial with fp32 scales
            #pragma unroll
            for (int mi = 0; mi < 2; mi++)
                #pragma unroll
                for (int ni = 0; ni < 2; ni++) {
                    float sh0 = sah4[2 * mi],     sl0 = sal4[2 * mi];
                    float sh1 = sah4[2 * mi + 1], sl1 = sal4[2 * mi + 1];
                    accM[mi][ni][0] += swv[ni].x * (sh0 * (float)accPh[mi][ni][0] + sl0 * (float)accPl[mi][ni][0]);
                    accM[mi][ni][1] += swv[ni].y * (sh0 * (float)accPh[mi][ni][1] + sl0 * (float)accPl[mi][ni][1]);
                    accM[mi][ni][2] += swv[ni].x * (sh1 * (float)accPh[mi][ni][2] + sl1 * (float)accPl[mi][ni][2]);
                    accM[mi][ni][3] += swv[ni].y * (sh1 * (float)accPh[mi][ni][3] + sl1 * (float)accPl[mi][ni][3]);
                    accPh[mi][ni][0] = 0; accPh[mi][ni][1] = 0; accPh[mi][ni][2] = 0; accPh[mi][ni][3] = 0;
                    accPl[mi][ni][0] = 0; accPl[mi][ni][1] = 0; accPl[mi][ni][2] = 0; accPl[mi][ni][3] = 0;
                }
        }
    }

    #pragma unroll
    for (int mi = 0; mi < 2; mi++) {
        int row = bm + wm * 32 + mi * 16 + (lane >> 2);
        #pragma unroll
        for (int ni = 0; ni < 2; ni++) {
            int col = colv[ni];
            float* p0 = C + (size_t)row * N + col;
            float* p1 = p0 + (size_t)8 * N;
            if (ACCF) {
                p0[0] += accM[mi][ni][0]; p0[1] += accM[mi][ni][1];
                p1[0] += accM[mi][ni][2]; p1[1] += accM[mi][ni][3];
            } else {
                p0[0] = accM[mi][ni][0]; p0[1] = accM[mi][ni][1];
                p1[0] = accM[mi][ni][2]; p1[1] = accM[mi][ni][3];
            }
        }
    }
}

// ---------------- flash-style tiled causal attention (f32 out) ----------------
__device__ __forceinline__ float rmax16(float v) {
    #pragma unroll
    for (int m = 1; m < 16; m <<= 1) v = fmaxf(v, __shfl_xor_sync(0xffffffffu, v, m));
    return v;
}
__device__ __forceinline__ float rsum16(float v) {
    #pragma unroll
    for (int m = 1; m < 16; m <<= 1) v += __shfl_xor_sync(0xffffffffu, v, m);
    return v;
}

__global__ __launch_bounds__(256)
void attn_flash(const float* __restrict__ qkv, const float* __restrict__ h,
                const float* __restrict__ alpha, float* __restrict__ o) {
    extern __shared__ float sm[];
    float (*Qs)[65] = (float(*)[65])sm;
    float (*Ks)[65] = (float(*)[65])(sm + 64 * 65);
    float (*Vs)[65] = (float(*)[65])(sm + 2 * 64 * 65);
    float (*Ps)[65] = (float(*)[65])(sm + 3 * 64 * 65);

    int qt = blockIdx.x;
    int bh = blockIdx.y;
    int b = bh >> 4, hh = bh & 15;
    int tid = threadIdx.x;
    int tx = tid & 15, ty = tid >> 4;

    const float* qb = qkv + (size_t)(b * SS + qt * 64) * 3072 + hh * 64;
    for (int i = tid; i < 64 * 64; i += 256)
        Qs[i >> 6][i & 63] = qb[(size_t)(i >> 6) * 3072 + (i & 63)];

    float m_run[4], l_run[4], O[4][4];
    #pragma unroll
    for (int i = 0; i < 4; i++) {
        m_run[i] = -3.4e38f; l_run[i] = 0.f;
        O[i][0] = O[i][1] = O[i][2] = O[i][3] = 0.f;
    }

    const float* kb = qkv + (size_t)b * SS * 3072 + 1024 + hh * 64;
    const float* vb = qkv + (size_t)b * SS * 3072 + 2048 + hh * 64;

    for (int kt = 0; kt <= qt; kt++) {
        __syncthreads();
        for (int i = tid; i < 64 * 64; i += 256) {
            int r = i >> 6, c = i & 63;
            size_t gr = (size_t)(kt * 64 + r) * 3072 + c;
            Ks[r][c] = kb[gr];
            Vs[r][c] = vb[gr];
        }
        __syncthreads();

        float s[4][4];
        #pragma unroll
        for (int i = 0; i < 4; i++) { s[i][0]=0.f; s[i][1]=0.f; s[i][2]=0.f; s[i][3]=0.f; }
        #pragma unroll 8
        for (int d = 0; d < 64; d++) {
            float a[4], bv[4];
            #pragma unroll
            for (int i = 0; i < 4; i++) a[i]  = Qs[ty * 4 + i][d];
            #pragma unroll
            for (int j = 0; j < 4; j++) bv[j] = Ks[tx * 4 + j][d];
            #pragma unroll
            for (int i = 0; i < 4; i++)
                #pragma unroll
                for (int j = 0; j < 4; j++) s[i][j] += a[i] * bv[j];
        }
        if (kt == qt) {
            #pragma unroll
            for (int i = 0; i < 4; i++) {
                int row = ty * 4 + i;
                #pragma unroll
                for (int j = 0; j < 4; j++)
                    if (tx * 4 + j > row) s[i][j] = -3.4e38f;
        } }
        #pragma unroll
        for (int i = 0; i < 4; i++) {
            float tm = fmaxf(fmaxf(s[i][0] * 0.125f, s[i][1] * 0.125f),
                             fmaxf(s[i][2] * 0.125f, s[i][3] * 0.125f));
            tm = rmax16(tm);
            float m_new = fmaxf(m_run[i], tm);
            float fac = expf(m_run[i] - m_new);
            float rs = 0.f;
            #pragma unroll
            for (int j = 0; j < 4; j++) {
                float p = expf(s[i][j] * 0.125f - m_new);
                Ps[ty * 4 + i][tx * 4 + j] = p;
                rs += p;
            }
            rs = rsum16(rs);
            l_run[i] = l_run[i] * fac + rs;
            m_run[i] = m_new;
            #pragma unroll
            for (int j = 0; j < 4; j++) O[i][j] *= fac;
        }
        __syncthreads();

        #pragma unroll 8
        for (int t = 0; t < 64; t++) {
            float a[4], bv[4];
            #pragma unroll
            for (int i = 0; i < 4; i++) a[i]  = Ps[ty * 4 + i][t];
            #pragma unroll
            for (int j = 0; j < 4; j++) bv[j] = Vs[t][tx * 4 + j];
            #pragma unroll
            for (int i = 0; i < 4; i++)
                #pragma unroll
                for (int j = 0; j < 4; j++) O[i][j] += a[i] * bv[j];
        }
    }

    float ah = alpha[hh];
    #pragma unroll
    for (int i = 0; i < 4; i++) {
        float inv = 1.f / l_run[i];
        int row = qt * 64 + ty * 4 + i;
        #pragma unroll
        for (int j = 0; j < 4; j++) {
            long idx = (long)(b * SS + row) * DD + hh * 64 + tx * 4 + j;
            o[idx] = O[i][j] * inv + ah * h[idx];
        }
    }
}

// ---------------- host launcher ----------------
extern "C" void kernel_launch(void* const* d_in, const int* in_sizes, int n_in,
                              void* d_out, int out_size) {
    (void)in_sizes; (void)n_in; (void)out_size;
    const int*   ids   = (const int*)  d_in[0];
    const void*  emb_t = d_in[1];
    const float* emb_s = (const float*)d_in[2];
    const void*  qt = d_in[3];  const float* qs = (const float*)d_in[4];
    const void*  kt = d_in[5];  const float* ks = (const float*)d_in[6];
    const void*  vt = d_in[7];  const float* vs = (const float*)d_in[8];
    const void*  ot = d_in[9];  const float* os = (const float*)d_in[10];
    const void*  gt = d_in[11]; const float* gs = (const float*)d_in[12];
    const void*  ut = d_in[13]; const float* us = (const float*)d_in[14];
    const void*  dt = d_in[15]; const float* ds = (const float*)d_in[16];
    const float* wa    = (const float*)d_in[17];
    const float* wm    = (const float*)d_in[18];
    const float* alpha = (const float*)d_in[19];
    const float* wf    = (const float*)d_in[20];
    const void*  ht = d_in[21]; const float* hs = (const float*)d_in[22];
    float* out = (float*)d_out;

    float *x, *h, *qkv, *gu, *o, *scb, *sah, *sal;
    int8_t *w8, *qh, *ql;
    cudaGetSymbolAddress((void**)&x,   g_x);
    cudaGetSymbolAddress((void**)&h,   g_h);
    cudaGetSymbolAddress((void**)&qkv, g_qkv);
    cudaGetSymbolAddress((void**)&gu,  g_gu);
    cudaGetSymbolAddress((void**)&o,   g_o);
    cudaGetSymbolAddress((void**)&w8,  g_w8);
    cudaGetSymbolAddress((void**)&scb, g_sc);
    cudaGetSymbolAddress((void**)&qh,  g_qh);
    cudaGetSymbolAddress((void**)&ql,  g_ql);
    cudaGetSymbolAddress((void**)&sah, g_sah);
    cudaGetSymbolAddress((void**)&sal, g_sal);

    cudaFuncSetAttribute(gemm2i<false>, cudaFuncAttributeMaxDynamicSharedMemorySize, GSMI);
    cudaFuncSetAttribute(gemm2i<true>,  cudaFuncAttributeMaxDynamicSharedMemorySize, GSMI);
    cudaFuncSetAttribute(attn_flash, cudaFuncAttributeMaxDynamicSharedMemorySize, 4 * 64 * 65 * 4);

    probe_kernel<<<1, 32>>>(emb_t);

    const long SZD = (long)DD * DD;       // 1,048,576
    const long SZF = (long)DFFN * DD;     // 4,194,304
    const long ngD = SZD / 128, ngF = SZF / 128;

    // weights -> exact int8 codes
    for (int l = 0; l < LLAY; l++) {
        convert_t8<<<1024, 256>>>(qt, l * SZD, OQKV + (long)l * 3 * SZD,           SZD);
        convert_t8<<<1024, 256>>>(kt, l * SZD, OQKV + (long)l * 3 * SZD + SZD,     SZD);
        convert_t8<<<1024, 256>>>(vt, l * SZD, OQKV + (long)l * 3 * SZD + 2 * SZD, SZD);
        convert_t8<<<1024, 256>>>(gt, l * SZF, OGU  + (long)l * 2 * SZF,           SZF);
        convert_t8<<<1024, 256>>>(ut, l * SZF, OGU  + (long)l * 2 * SZF + SZF,     SZF);
    }
    convert_t8<<<1024, 256>>>(ot, 0, OO,  (long)LLAY * SZD);
    convert_t8<<<1024, 256>>>(dt, 0, ODW, (long)LLAY * SZF);
    convert_t8<<<2048, 256>>>(ht, 0, OHD, (long)VV * DD);

    // weight scales -> transposed [g][N] per GEMM tensor
    for (int l = 0; l < LLAY; l++) {
        long bq = (OQKV + (long)l * 3 * SZD) / 128;
        transp_sc<<<32, 256>>>(qs, l * ngD, bq, DD, 8, 3 * DD, 0);
        transp_sc<<<32, 256>>>(ks, l * ngD, bq, DD, 8, 3 * DD, DD);
        transp_sc<<<32, 256>>>(vs, l * ngD, bq, DD, 8, 3 * DD, 2 * DD);
        long bg = (OGU + (long)l * 2 * SZF) / 128;
        transp_sc<<<64, 256>>>(gs, l * ngF, bg, DFFN, 8, 2 * DFFN, 0);
        transp_sc<<<64, 256>>>(us, l * ngF, bg, DFFN, 8, 2 * DFFN, DFFN);
        transp_sc<<<32, 256>>>(os, l * ngD, (OO  + (long)l * SZD) / 128, DD, 8,  DD, 0);
        transp_sc<<<64, 256>>>(ds, l * ngF, (ODW + (long)l * SZF) / 128, DD, 32, DD, 0);
    }
    transp_sc<<<256, 256>>>(hs, 0, OHD / 128, VV, 8, VV, 0);

    embed_kernel<<<MM, 256>>>(ids, emb_t, emb_s, x);

    const size_t asmem = 4 * 64 * 65 * 4;

    for (int l = 0; l < LLAY; l++) {
        long oqkv = OQKV + (long)l * 3 * SZD;
        long oo   = OO   + (long)l * SZD;
        long ogu  = OGU  + (long)l * 2 * SZF;
        long odw  = ODW  + (long)l * SZF;

        rmsnorm_q<<<MM, 256>>>(x, wa + (long)l * DD, h, qh, ql, sah, sal);
        gemm2i<false><<<dim3(48, 16), 512, GSMI>>>(qh, ql, sah, sal, w8 + oqkv, scb + oqkv / 128, qkv, MM, 3 * DD, DD);
        attn_flash<<<dim3(SS / 64, BB * HH), 256, asmem>>>(qkv, h, alpha + (long)l * HH, o);
        quant_act<<<MM, 256>>>(o, qh, ql, sah, sal);
        gemm2i<true><<<dim3(16, 16), 512, GSMI>>>(qh, ql, sah, sal, w8 + oo, scb + oo / 128, x, MM, DD, DD);

        rmsnorm_q<<<MM, 256>>>(x, wm + (long)l * DD, nullptr, qh, ql, sah, sal);
        gemm2i<false><<<dim3(128, 16), 512, GSMI>>>(qh, ql, sah, sal, w8 + ogu, scb + ogu / 128, gu, MM, 2 * DFFN, DD);
        silumul_q<<<dim3(4, MM), 256>>>(gu, qh, ql, sah, sal);
        gemm2i<true><<<dim3(16, 16), 512, GSMI>>>(qh, ql, sah, sal, w8 + odw, scb + odw / 128, x, MM, DD, DFFN);
    }

    rmsnorm_q<<<MM, 256>>>(x, wf, nullptr, qh, ql, sah, sal);
    gemm2i<false><<<dim3(500, 16), 512, GSMI>>>(qh, ql, sah, sal, w8 + OHD, scb + OHD / 128, out, MM, VV, DD);
}

// round 14
// speedup vs baseline: 2.2355x; 2.2355x over previous
#include <cuda_runtime.h>
#include <cuda_bf16.h>
#include <cuda_fp16.h>
#include <cstdint>

using bf16 = __nv_bfloat16;

// ---------------- problem dims ----------------
#define BB   2
#define SS   1024
#define DD   1024
#define HH   16
#define DFFN 4096
#define LLAY 2
#define VV   32000
#define MM   (BB*SS)

// ---------------- ternary weight buffer (bf16, EXACT codes) ----------------
#define OQKV 0L
#define OO   (OQKV + (long)LLAY*3*DD*DD)
#define OGU  (OO   + (long)LLAY*DD*DD)
#define ODW  (OGU  + (long)LLAY*2*DFFN*DD)
#define OHD  (ODW  + (long)LLAY*DD*DFFN)
#define WTOT (OHD  + (long)VV*DD)

__device__ bf16  g_wt[WTOT];          // ternary codes as bf16 (exact); head region unused
__device__ __half g_wh[(long)VV*DD];  // head ternary codes as fp16 (exact)
__device__ float g_sc[WTOT/128];      // per-group scales, packed to match g_wt
__device__ int   g_wtype;

// ---------------- activation scratch ----------------
__device__ float g_x[MM*DD];
__device__ float g_h[MM*DD];
__device__ float g_qkv[(size_t)MM*3*DD];
__device__ float g_gu[(size_t)MM*2*DFFN];
__device__ bf16  g_hhi[MM*DD],  g_hlo[MM*DD];
__device__ bf16  g_ohi[MM*DD],  g_olo[MM*DD];
__device__ bf16  g_ghi[(size_t)MM*DFFN], g_glo[(size_t)MM*DFFN];
__device__ __half g_hh[MM*DD];        // fp16 final-norm activations for head

// ---------------- dtype probe ----------------
__global__ void probe_kernel(const void* raw) {
    if (threadIdx.x != 0) return;
    const unsigned* pw = (const unsigned*)raw;
    bool is_i32 = true;
    for (int i = 0; i < 256; i++) {
        unsigned w = pw[i];
        if (!(w == 0u || w == 1u || w == 0xFFFFFFFFu)) { is_i32 = false; break; }
    }
    if (is_i32) { g_wtype = 1; return; }
    bool is_f32 = true;
    for (int i = 0; i < 256; i++) {
        unsigned w = pw[i];
        if (!(w == 0u || w == 0x3F800000u || w == 0xBF800000u)) { is_f32 = false; break; }
    }
    if (is_f32) { g_wtype = 2; return; }
    const unsigned short* ph = (const unsigned short*)raw;
    bool is_b16 = true;
    for (int i = 0; i < 512; i++) {
        unsigned short w = ph[i];
        if (!(w == 0u || w == 0x3F80u || w == 0xBF80u)) { is_b16 = false; break; }
    }
    g_wtype = is_b16 ? 3 : 0;
}

__device__ __forceinline__ float load_tern(const void* p, long i, int t) {
    if (t == 1) return (float)((const int*)p)[i];
    if (t == 2) return ((const float*)p)[i];
    if (t == 3) return __bfloat162float(((const bf16*)p)[i]);
    return (float)((const int8_t*)p)[i];
}

// ---------------- weight convert: exact int -> bf16 ----------------
struct alignas(16) B8 { bf16 v[8]; };

__global__ void convert_t(const void* __restrict__ src, long srcOff, long dstOff, long n) {
    int t = g_wtype;
    if (t == 1) {
        long stride = (long)gridDim.x * blockDim.x * 8;
        for (long i = ((long)blockIdx.x * blockDim.x + threadIdx.x) * 8; i < n; i += stride) {
            const int4* p = (const int4*)((const int*)src + srcOff + i);
            int4 a = p[0], b = p[1];
            B8 o;
            o.v[0] = __float2bfloat16((float)a.x); o.v[1] = __float2bfloat16((float)a.y);
            o.v[2] = __float2bfloat16((float)a.z); o.v[3] = __float2bfloat16((float)a.w);
            o.v[4] = __float2bfloat16((float)b.x); o.v[5] = __float2bfloat16((float)b.y);
            o.v[6] = __float2bfloat16((float)b.z); o.v[7] = __float2bfloat16((float)b.w);
            *(B8*)(g_wt + dstOff + i) = o;
        }
    } else {
        long stride = (long)gridDim.x * blockDim.x;
        for (long i = (long)blockIdx.x * blockDim.x + threadIdx.x; i < n; i += stride)
            g_wt[dstOff + i] = __float2bfloat16(load_tern(src, srcOff + i, t));
    }
}

// ---------------- head weight convert: exact int -> fp16 ----------------
struct alignas(16) H8 { __half v[8]; };
__global__ void convert_th(const void* __restrict__ src, long n) {
    int t = g_wtype;
    if (t == 1) {
        long stride = (long)gridDim.x * blockDim.x * 8;
        for (long i = ((long)blockIdx.x * blockDim.x + threadIdx.x) * 8; i < n; i += stride) {
            const int4* p = (const int4*)((const int*)src + i);
            int4 a = p[0], b = p[1];
            H8 o;
            o.v[0] = __float2half((float)a.x); o.v[1] = __float2half((float)a.y);
            o.v[2] = __float2half((float)a.z); o.v[3] = __float2half((float)a.w);
            o.v[4] = __float2half((float)b.x); o.v[5] = __float2half((float)b.y);
            o.v[6] = __float2half((float)b.z); o.v[7] = __float2half((float)b.w);
            *(H8*)(g_wh + i) = o;
        }
    } else {
        long stride = (long)gridDim.x * blockDim.x;
        for (long i = (long)blockIdx.x * blockDim.x + threadIdx.x; i < n; i += stride)
            g_wh[i] = __float2half(load_tern(src, i, t));
    }
}

// ---------------- scale copy into packed layout ----------------
__global__ void copy_sc(const float* __restrict__ src, long srcOff, long dstOff, long n) {
    long stride = (long)gridDim.x * blockDim.x * 4;
    for (long i = ((long)blockIdx.x * blockDim.x + threadIdx.x) * 4; i < n; i += stride) {
        float4 v = *(const float4*)(src + srcOff + i);
        *(float4*)(g_sc + dstOff + i) = v;
    }
}

// ---------------- embedding ----------------
__global__ void embed_kernel(const int* __restrict__ ids, const void* __restrict__ et,
                             const float* __restrict__ es, float* __restrict__ x) {
    int t = g_wtype;
    int m = blockIdx.x;
    long base = (long)ids[m] * DD;
    for (int d = threadIdx.x; d < DD; d += blockDim.x) {
        long idx = base + d;
        x[(long)m * DD + d] = load_tern(et, idx, t) * es[idx >> 7];
    }
}

// ---------------- rmsnorm + bf16 hi/lo split ----------------
__global__ void rmsnorm_split(const float* __restrict__ x, const float* __restrict__ w,
                              float* __restrict__ h, bf16* __restrict__ hi, bf16* __restrict__ lo) {
    int m = blockIdx.x;
    const float* xr = x + (long)m * DD;
    float ss = 0.f;
    for (int d = threadIdx.x; d < DD; d += blockDim.x) { float v = xr[d]; ss += v * v; }
    __shared__ float red[256];
    red[threadIdx.x] = ss; __syncthreads();
    #pragma unroll
    for (int st = 128; st > 0; st >>= 1) {
        if (threadIdx.x < st) red[threadIdx.x] += red[threadIdx.x + st];
        __syncthreads();
    }
    float r = rsqrtf(red[0] * (1.0f / DD) + 1e-6f);
    for (int d = threadIdx.x; d < DD; d += blockDim.x) {
        long i = (long)m * DD + d;
        float y = xr[d] * r * w[d];
        if (h) h[i] = y;
        bf16 yh = __float2bfloat16(y);
        hi[i] = yh;
        lo[i] = __float2bfloat16(y - __bfloat162float(yh));
    }
}

// ---------------- final rmsnorm -> single fp16 (head path) ----------------
__global__ void rmsnorm_h(const float* __restrict__ x, const float* __restrict__ w,
                          __half* __restrict__ hq) {
    int m = blockIdx.x;
    const float* xr = x + (long)m * DD;
    float ss = 0.f;
    for (int d = threadIdx.x; d < DD; d += blockDim.x) { float v = xr[d]; ss += v * v; }
    __shared__ float red[256];
    red[threadIdx.x] = ss; __syncthreads();
    #pragma unroll
    for (int st = 128; st > 0; st >>= 1) {
        if (threadIdx.x < st) red[threadIdx.x] += red[threadIdx.x + st];
        __syncthreads();
    }
    float r = rsqrtf(red[0] * (1.0f / DD) + 1e-6f);
    for (int d = threadIdx.x; d < DD; d += blockDim.x) {
        long i = (long)m * DD + d;
        hq[i] = __float2half(xr[d] * r * w[d]);
    }
}

// ---------------- mma.sync helpers ----------------
__device__ __forceinline__ void cpa16(uint32_t d, const void* s) {
    asm volatile("cp.async.ca.shared.global [%0], [%1], 16;\n" :: "r"(d), "l"(s));
}
__device__ __forceinline__ void ldsm4(uint32_t* r, uint32_t a) {
    asm volatile("ldmatrix.sync.aligned.m8n8.x4.shared.b16 {%0,%1,%2,%3},[%4];"
                 : "=r"(r[0]), "=r"(r[1]), "=r"(r[2]), "=r"(r[3]) : "r"(a));
}
__device__ __forceinline__ void ldsm2(uint32_t* r, uint32_t a) {
    asm volatile("ldmatrix.sync.aligned.m8n8.x2.shared.b16 {%0,%1},[%2];"
                 : "=r"(r[0]), "=r"(r[1]) : "r"(a));
}
__device__ __forceinline__ void mma16816(float* c, const uint32_t* a, const uint32_t* b) {
    asm volatile("mma.sync.aligned.m16n8k16.row.col.f32.bf16.bf16.f32 "
                 "{%0,%1,%2,%3},{%4,%5,%6,%7},{%8,%9},{%0,%1,%2,%3};"
                 : "+f"(c[0]), "+f"(c[1]), "+f"(c[2]), "+f"(c[3])
                 : "r"(a[0]), "r"(a[1]), "r"(a[2]), "r"(a[3]), "r"(b[0]), "r"(b[1]));
}
__device__ __forceinline__ void mma16816h(float* c, const uint32_t* a, const uint32_t* b) {
    asm volatile("mma.sync.aligned.m16n8k16.row.col.f32.f16.f16.f32 "
                 "{%0,%1,%2,%3},{%4,%5,%6,%7},{%8,%9},{%0,%1,%2,%3};"
                 : "+f"(c[0]), "+f"(c[1]), "+f"(c[2]), "+f"(c[3])
                 : "r"(a[0]), "r"(a[1]), "r"(a[2]), "r"(a[3]), "r"(b[0]), "r"(b[1]));
}

// ---------------- 2-product group-scaled GEMM (bf16) — R11 proven config ----------------
#define STG2_B 30720
#define NSTG   4
#define GSM2   (NSTG*STG2_B)

template<bool ACCF>
__global__ __launch_bounds__(512, 1)
void gemm2_kernel(const bf16* __restrict__ Ah, const bf16* __restrict__ Al,
                  const bf16* __restrict__ T,  const float* __restrict__ sc,
                  float* __restrict__ C, int M, int N, int K) {
    extern __shared__ char smem_raw[];
    const uint32_t sbase = (uint32_t)__cvta_generic_to_shared(smem_raw);
    const int tid = threadIdx.x, lane = tid & 31, wid = tid >> 5;
    const int wm = wid >> 2, wn = wid & 3;
    const int bm = blockIdx.y * 128, bn = blockIdx.x * 128;
    const int Kg = K >> 7;
    const int r0 = tid >> 2, cc = (tid & 3) * 8;

    int aoffE[2], boffE[4];
    {
        int r = lane & 15, kh = (lane >> 4) * 8;
        #pragma unroll
        for (int mi = 0; mi < 2; mi++) aoffE[mi] = (wm * 32 + mi * 16 + r) * 40 + kh;
        #pragma unroll
        for (int ni = 0; ni < 4; ni++) boffE[ni] = (wn * 32 + ni * 8 + (r & 7)) * 40 + ((r >> 3) * 8);
    }

    float accM[2][4][4], accP[2][4][4];
    #pragma unroll
    for (int i = 0; i < 2; i++)
        #pragma unroll
        for (int j = 0; j < 4; j++)
            #pragma unroll
            for (int c = 0; c < 4; c++) { accM[i][j][c] = 0.f; accP[i][j][c] = 0.f; }

    auto load_stage = [&](int kt) {
        uint32_t sb = sbase + (kt & (NSTG - 1)) * STG2_B;
        uint32_t d = r0 * 80 + cc * 2;
        size_t ga = (size_t)(bm + r0) * K + (size_t)kt * 32 + cc;
        size_t gb = (size_t)(bn + r0) * K + (size_t)kt * 32 + cc;
        cpa16(sb + d,         Ah + ga);
        cpa16(sb + 10240 + d, Al + ga);
        cpa16(sb + 20480 + d, T + gb);
    };

    const int KT = K >> 5;
    load_stage(0); asm volatile("cp.async.commit_group;\n" ::: "memory");
    load_stage(1); asm volatile("cp.async.commit_group;\n" ::: "memory");
    load_stage(2); asm volatile("cp.async.commit_group;\n" ::: "memory");

    for (int kt = 0; kt < KT; kt++) {
        asm volatile("cp.async.wait_group 2;\n" ::: "memory");
        __syncthreads();
        if (kt + 3 < KT) load_stage(kt + 3);
        asm volatile("cp.async.commit_group;\n" ::: "memory");

        uint32_t sb = sbase + (kt & (NSTG - 1)) * STG2_B;
        #pragma unroll
        for (int kk = 0; kk < 2; kk++) {
            const int kb = kk * 32;
            uint32_t a[2][4], b[4][2];
            #pragma unroll
            for (int ni = 0; ni < 4; ni++) ldsm2(b[ni], sb + 20480 + boffE[ni] * 2 + kb);
            #pragma unroll
            for (int mi = 0; mi < 2; mi++) ldsm4(a[mi], sb + aoffE[mi] * 2 + kb);
            #pragma unroll
            for (int mi = 0; mi < 2; mi++)
                #pragma unroll
                for (int ni = 0; ni < 4; ni++) mma16816(accP[mi][ni], a[mi], b[ni]);
            #pragma unroll
            for (int mi = 0; mi < 2; mi++) ldsm4(a[mi], sb + 10240 + aoffE[mi] * 2 + kb);
            #pragma unroll
            for (int mi = 0; mi < 2; mi++)
                #pragma unroll
                for (int ni = 0; ni < 4; ni++) mma16816(accP[mi][ni], a[mi], b[ni]);
        }

        if ((kt & 3) == 3) {
            int g = kt >> 2;
            #pragma unroll
            for (int ni = 0; ni < 4; ni++) {
                int col = bn + wn * 32 + ni * 8 + (lane & 3) * 2;
                float s0 = __ldg(sc + (size_t)col * Kg + g);
                float s1 = __ldg(sc + (size_t)(col + 1) * Kg + g);
                #pragma unroll
                for (int mi = 0; mi < 2; mi++) {
                    accM[mi][ni][0] += s0 * accP[mi][ni][0];
                    accM[mi][ni][1] += s1 * accP[mi][ni][1];
                    accM[mi][ni][2] += s0 * accP[mi][ni][2];
                    accM[mi][ni][3] += s1 * accP[mi][ni][3];
                    accP[mi][ni][0] = 0.f; accP[mi][ni][1] = 0.f;
                    accP[mi][ni][2] = 0.f; accP[mi][ni][3] = 0.f;
                }
            }
        }
    }

    #pragma unroll
    for (int mi = 0; mi < 2; mi++) {
        int row = bm + wm * 32 + mi * 16 + (lane >> 2);
        #pragma unroll
        for (int ni = 0; ni < 4; ni++) {
            int col = bn + wn * 32 + ni * 8 + (lane & 3) * 2;
            float* p0 = C + (size_t)row * N + col;
            float* p1 = p0 + (size_t)8 * N;
            if (ACCF) {
                p0[0] += accM[mi][ni][0]; p0[1] += accM[mi][ni][1];
                p1[0] += accM[mi][ni][2]; p1[1] += accM[mi][ni][3];
            } else {
                p0[0] = accM[mi][ni][0]; p0[1] = accM[mi][ni][1];
                p1[0] = accM[mi][ni][2]; p1[1] = accM[mi][ni][3];
            }
        }
    }
}

// ---------------- 1-product group-scaled GEMM (fp16) — head only ----------------
#define STG1_B 20480
#define GSM1   (NSTG*STG1_B)

__global__ __launch_bounds__(512, 1)
void gemm1h_kernel(const __half* __restrict__ Ah, const __half* __restrict__ T,
                   const float* __restrict__ sc, float* __restrict__ C,
                   int M, int N, int K) {
    extern __shared__ char smem_raw[];
    const uint32_t sbase = (uint32_t)__cvta_generic_to_shared(smem_raw);
    const int tid = threadIdx.x, lane = tid & 31, wid = tid >> 5;
    const int wm = wid >> 2, wn = wid & 3;
    const int bm = blockIdx.y * 128, bn = blockIdx.x * 128;
    const int Kg = K >> 7;
    const int r0 = tid >> 2, cc = (tid & 3) * 8;

    int aoffE[2], boffE[4];
    {
        int r = lane & 15, kh = (lane >> 4) * 8;
        #pragma unroll
        for (int mi = 0; mi < 2; mi++) aoffE[mi] = (wm * 32 + mi * 16 + r) * 40 + kh;
        #pragma unroll
        for (int ni = 0; ni < 4; ni++) boffE[ni] = (wn * 32 + ni * 8 + (r & 7)) * 40 + ((r >> 3) * 8);
    }

    float accM[2][4][4], accP[2][4][4];
    #pragma unroll
    for (int i = 0; i < 2; i++)
        #pragma unroll
        for (int j = 0; j < 4; j++)
            #pragma unroll
            for (int c = 0; c < 4; c++) { accM[i][j][c] = 0.f; accP[i][j][c] = 0.f; }

    auto load_stage = [&](int kt) {
        uint32_t sb = sbase + (kt & (NSTG - 1)) * STG1_B;
        uint32_t d = r0 * 80 + cc * 2;
        size_t ga = (size_t)(bm + r0) * K + (size_t)kt * 32 + cc;
        size_t gb = (size_t)(bn + r0) * K + (size_t)kt * 32 + cc;
        cpa16(sb + d,         Ah + ga);
        cpa16(sb + 10240 + d, T + gb);
    };

    const int KT = K >> 5;
    load_stage(0); asm volatile("cp.async.commit_group;\n" ::: "memory");
    load_stage(1); asm volatile("cp.async.commit_group;\n" ::: "memory");
    load_stage(2); asm volatile("cp.async.commit_group;\n" ::: "memory");

    for (int kt = 0; kt < KT; kt++) {
        asm volatile("cp.async.wait_group 2;\n" ::: "memory");
        __syncthreads();
        if (kt + 3 < KT) load_stage(kt + 3);
        asm volatile("cp.async.commit_group;\n" ::: "memory");

        uint32_t sb = sbase + (kt & (NSTG - 1)) * STG1_B;
        #pragma unroll
        for (int kk = 0; kk < 2; kk++) {
            const int kb = kk * 32;
            uint32_t a[2][4], b[4][2];
            #pragma unroll
            for (int ni = 0; ni < 4; ni++) ldsm2(b[ni], sb + 10240 + boffE[ni] * 2 + kb);
            #pragma unroll
            for (int mi = 0; mi < 2; mi++) ldsm4(a[mi], sb + aoffE[mi] * 2 + kb);
            #pragma unroll
            for (int mi = 0; mi < 2; mi++)
                #pragma unroll
                for (int ni = 0; ni < 4; ni++) mma16816h(accP[mi][ni], a[mi], b[ni]);
        }

        if ((kt & 3) == 3) {
            int g = kt >> 2;
            #pragma unroll
            for (int ni = 0; ni < 4; ni++) {
                int col = bn + wn * 32 + ni * 8 + (lane & 3) * 2;
                float s0 = __ldg(sc + (size_t)col * Kg + g);
                float s1 = __ldg(sc + (size_t)(col + 1) * Kg + g);
                #pragma unroll
                for (int mi = 0; mi < 2; mi++) {
                    accM[mi][ni][0] += s0 * accP[mi][ni][0];
                    accM[mi][ni][1] += s1 * accP[mi][ni][1];
                    accM[mi][ni][2] += s0 * accP[mi][ni][2];
                    accM[mi][ni][3] += s1 * accP[mi][ni][3];
                    accP[mi][ni][0] = 0.f; accP[mi][ni][1] = 0.f;
                    accP[mi][ni][2] = 0.f; accP[mi][ni][3] = 0.f;
                }
            }
        }
    }

    #pragma unroll
    for (int mi = 0; mi < 2; mi++) {
        int row = bm + wm * 32 + mi * 16 + (lane >> 2);
        #pragma unroll
        for (int ni = 0; ni < 4; ni++) {
            int col = bn + wn * 32 + ni * 8 + (lane & 3) * 2;
            float* p0 = C + (size_t)row * N + col;
            float* p1 = p0 + (size_t)8 * N;
            p0[0] = accM[mi][ni][0]; p0[1] = accM[mi][ni][1];
            p1[0] = accM[mi][ni][2]; p1[1] = accM[mi][ni][3];
        }
    }
}

// ---------------- flash-style tiled causal attention ----------------
__device__ __forceinline__ float rmax16(float v) {
    #pragma unroll
    for (int m = 1; m < 16; m <<= 1) v = fmaxf(v, __shfl_xor_sync(0xffffffffu, v, m));
    return v;
}
__device__ __forceinline__ float rsum16(float v) {
    #pragma unroll
    for (int m = 1; m < 16; m <<= 1) v += __shfl_xor_sync(0xffffffffu, v, m);
    return v;
}

__global__ __launch_bounds__(256)
void attn_flash(const float* __restrict__ qkv, const float* __restrict__ h,
                const float* __restrict__ alpha, bf16* __restrict__ ohi, bf16* __restrict__ olo) {
    extern __shared__ float sm[];
    float (*Qs)[65] = (float(*)[65])sm;
    float (*Ks)[65] = (float(*)[65])(sm + 64 * 65);
    float (*Vs)[65] = (float(*)[65])(sm + 2 * 64 * 65);
    float (*Ps)[65] = (float(*)[65])(sm + 3 * 64 * 65);

    int qt = blockIdx.x;
    int bh = blockIdx.y;
    int b = bh >> 4, hh = bh & 15;
    int tid = threadIdx.x;
    int tx = tid & 15, ty = tid >> 4;

    const float* qb = qkv + (size_t)(b * SS + qt * 64) * 3072 + hh * 64;
    for (int i = tid; i < 64 * 64; i += 256)
        Qs[i >> 6][i & 63] = qb[(size_t)(i >> 6) * 3072 + (i & 63)];

    float m_run[4], l_run[4], O[4][4];
    #pragma unroll
    for (int i = 0; i < 4; i++) {
        m_run[i] = -3.4e38f; l_run[i] = 0.f;
        O[i][0] = O[i][1] = O[i][2] = O[i][3] = 0.f;
    }

    const float* kb = qkv + (size_t)b * SS * 3072 + 1024 + hh * 64;
    const float* vb = qkv + (size_t)b * SS * 3072 + 2048 + hh * 64;

    for (int kt = 0; kt <= qt; kt++) {
        __syncthreads();
        for (int i = tid; i < 64 * 64; i += 256) {
            int r = i >> 6, c = i & 63;
            size_t gr = (size_t)(kt * 64 + r) * 3072 + c;
            Ks[r][c] = kb[gr];
            Vs[r][c] = vb[gr];
        }
        __syncthreads();

        float s[4][4];
        #pragma unroll
        for (int i = 0; i < 4; i++) { s[i][0]=0.f; s[i][1]=0.f; s[i][2]=0.f; s[i][3]=0.f; }
        #pragma unroll 8
        for (int d = 0; d < 64; d++) {
            float a[4], bv[4];
            #pragma unroll
            for (int i = 0; i < 4; i++) a[i]  = Qs[ty * 4 + i][d];
            #pragma unroll
            for (int j = 0; j < 4; j++) bv[j] = Ks[tx * 4 + j][d];
            #pragma unroll
            for (int i = 0; i < 4; i++)
                #pragma unroll
                for (int j = 0; j < 4; j++) s[i][j] += a[i] * bv[j];
        }
        if (kt == qt) {
            #pragma unroll
            for (int i = 0; i < 4; i++) {
                int row = ty * 4 + i;
                #pragma unroll
                for (int j = 0; j < 4; j++)
                    if (tx * 4 + j > row) s[i][j] = -3.4e38f;
        } }
        #pragma unroll
        for (int i = 0; i < 4; i++) {
            float tm = fmaxf(fmaxf(s[i][0] * 0.125f, s[i][1] * 0.125f),
                             fmaxf(s[i][2] * 0.125f, s[i][3] * 0.125f));
            tm = rmax16(tm);
            float m_new = fmaxf(m_run[i], tm);
            float fac = expf(m_run[i] - m_new);
            float rs = 0.f;
            #pragma unroll
            for (int j = 0; j < 4; j++) {
                float p = expf(s[i][j] * 0.125f - m_new);
                Ps[ty * 4 + i][tx * 4 + j] = p;
                rs += p;
            }
            rs = rsum16(rs);
            l_run[i] = l_run[i] * fac + rs;
            m_run[i] = m_new;
            #pragma unroll
            for (int j = 0; j < 4; j++) O[i][j] *= fac;
        }
        __syncthreads();

        #pragma unroll 8
        for (int t = 0; t < 64; t++) {
            float a[4], bv[4];
            #pragma unroll
            for (int i = 0; i < 4; i++) a[i]  = Ps[ty * 4 + i][t];
            #pragma unroll
            for (int j = 0; j < 4; j++) bv[j] = Vs[t][tx * 4 + j];
            #pragma unroll
            for (int i = 0; i < 4; i++)
                #pragma unroll
                for (int j = 0; j < 4; j++) O[i][j] += a[i] * bv[j];
        }
    }

    float ah = alpha[hh];
    #pragma unroll
    for (int i = 0; i < 4; i++) {
        float inv = 1.f / l_run[i];
        int row = qt * 64 + ty * 4 + i;
        #pragma unroll
        for (int j = 0; j < 4; j++) {
            long idx = (long)(b * SS + row) * DD + hh * 64 + tx * 4 + j;
            float val = O[i][j] * inv + ah * h[idx];
            bf16 vh = __float2bfloat16(val);
            ohi[idx] = vh;
            olo[idx] = __float2bfloat16(val - __bfloat162float(vh));
        }
    }
}

// ---------------- silu(g)*u, split (vectorized x4) ----------------
struct alignas(8) B4 { bf16 v[4]; };
__global__ void silumul_split(const float* __restrict__ gu, bf16* __restrict__ ghi, bf16* __restrict__ glo) {
    long i = ((long)blockIdx.x * 256 + threadIdx.x) * 4;
    long m = i >> 12, j = i & 4095;
    float4 a4 = *(const float4*)(gu + (m << 13) + j);
    float4 u4 = *(const float4*)(gu + (m << 13) + 4096 + j);
    float av[4] = {a4.x, a4.y, a4.z, a4.w};
    float uv[4] = {u4.x, u4.y, u4.z, u4.w};
    B4 hi, lo;
    #pragma unroll
    for (int c = 0; c < 4; c++) {
        float val = av[c] / (1.f + expf(-av[c])) * uv[c];
        bf16 vh = __float2bfloat16(val);
        hi.v[c] = vh;
        lo.v[c] = __float2bfloat16(val - __bfloat162float(vh));
    }
    *(B4*)(ghi + i) = hi;
    *(B4*)(glo + i) = lo;
}

// ---------------- host launcher ----------------
extern "C" void kernel_launch(void* const* d_in, const int* in_sizes, int n_in,
                              void* d_out, int out_size) {
    (void)in_sizes; (void)n_in; (void)out_size;
    const int*   ids   = (const int*)  d_in[0];
    const void*  emb_t = d_in[1];
    const float* emb_s = (const float*)d_in[2];
    const void*  qt = d_in[3];  const float* qs = (const float*)d_in[4];
    const void*  kt = d_in[5];  const float* ks = (const float*)d_in[6];
    const void*  vt = d_in[7];  const float* vs = (const float*)d_in[8];
    const void*  ot = d_in[9];  const float* os = (const float*)d_in[10];
    const void*  gt = d_in[11]; const float* gs = (const float*)d_in[12];
    const void*  ut = d_in[13]; const float* us = (const float*)d_in[14];
    const void*  dt = d_in[15]; const float* ds = (const float*)d_in[16];
    const float* wa    = (const float*)d_in[17];
    const float* wm    = (const float*)d_in[18];
    const float* alpha = (const float*)d_in[19];
    const float* wf    = (const float*)d_in[20];
    const void*  ht = d_in[21]; const float* hs = (const float*)d_in[22];
    float* out = (float*)d_out;

    float *x, *h, *qkv, *gu, *scb;
    bf16 *wt, *hhi, *hlo, *ohi, *olo, *ghi, *glo;
    __half *wh, *hh;
    cudaGetSymbolAddress((void**)&x,   g_x);
    cudaGetSymbolAddress((void**)&h,   g_h);
    cudaGetSymbolAddress((void**)&qkv, g_qkv);
    cudaGetSymbolAddress((void**)&gu,  g_gu);
    cudaGetSymbolAddress((void**)&wt,  g_wt);
    cudaGetSymbolAddress((void**)&wh,  g_wh);
    cudaGetSymbolAddress((void**)&scb, g_sc);
    cudaGetSymbolAddress((void**)&hhi, g_hhi);
    cudaGetSymbolAddress((void**)&hlo, g_hlo);
    cudaGetSymbolAddress((void**)&ohi, g_ohi);
    cudaGetSymbolAddress((void**)&olo, g_olo);
    cudaGetSymbolAddress((void**)&ghi, g_ghi);
    cudaGetSymbolAddress((void**)&glo, g_glo);
    cudaGetSymbolAddress((void**)&hh,  g_hh);

    cudaFuncSetAttribute(gemm2_kernel<false>, cudaFuncAttributeMaxDynamicSharedMemorySize, GSM2);
    cudaFuncSetAttribute(gemm2_kernel<true>,  cudaFuncAttributeMaxDynamicSharedMemorySize, GSM2);
    cudaFuncSetAttribute(gemm1h_kernel, cudaFuncAttributeMaxDynamicSharedMemorySize, GSM1);
    cudaFuncSetAttribute(attn_flash, cudaFuncAttributeMaxDynamicSharedMemorySize, 4 * 64 * 65 * 4);

    probe_kernel<<<1, 32>>>(emb_t);

    const long SZD = (long)DD * DD;       // 1,048,576
    const long SZF = (long)DFFN * DD;     // 4,194,304
    const long ngD = SZD / 128, ngF = SZF / 128;

    // weights -> exact bf16 codes (layer GEMMs) + fp16 codes (head)
    for (int l = 0; l < LLAY; l++) {
        convert_t<<<1024, 256>>>(qt, l * SZD, OQKV + (long)l * 3 * SZD,           SZD);
        convert_t<<<1024, 256>>>(kt, l * SZD, OQKV + (long)l * 3 * SZD + SZD,     SZD);
        convert_t<<<1024, 256>>>(vt, l * SZD, OQKV + (long)l * 3 * SZD + 2 * SZD, SZD);
        convert_t<<<1024, 256>>>(gt, l * SZF, OGU  + (long)l * 2 * SZF,           SZF);
        convert_t<<<1024, 256>>>(ut, l * SZF, OGU  + (long)l * 2 * SZF + SZF,     SZF);
    }
    convert_t<<<1024, 256>>>(ot, 0, OO,  (long)LLAY * SZD);
    convert_t<<<1024, 256>>>(dt, 0, ODW, (long)LLAY * SZF);
    convert_th<<<2048, 256>>>(ht, (long)VV * DD);

    // scales -> packed layout matching weight offsets (head scales at OHD/128)
    for (int l = 0; l < LLAY; l++) {
        copy_sc<<<64, 256>>>(qs, l * ngD, (OQKV + (long)l * 3 * SZD) / 128,           ngD);
        copy_sc<<<64, 256>>>(ks, l * ngD, (OQKV + (long)l * 3 * SZD + SZD) / 128,     ngD);
        copy_sc<<<64, 256>>>(vs, l * ngD, (OQKV + (long)l * 3 * SZD + 2 * SZD) / 128, ngD);
        copy_sc<<<64, 256>>>(gs, l * ngF, (OGU + (long)l * 2 * SZF) / 128,            ngF);
        copy_sc<<<64, 256>>>(us, l * ngF, (OGU + (long)l * 2 * SZF + SZF) / 128,      ngF);
    }
    copy_sc<<<64, 256>>>(os, 0, OO / 128,  (long)LLAY * ngD);
    copy_sc<<<128, 256>>>(ds, 0, ODW / 128, (long)LLAY * ngF);
    copy_sc<<<256, 256>>>(hs, 0, OHD / 128, (long)VV * DD / 128);

    embed_kernel<<<MM, 256>>>(ids, emb_t, emb_s, x);

    const size_t asmem = 4 * 64 * 65 * 4;

    for (int l = 0; l < LLAY; l++) {
        long oqkv = OQKV + (long)l * 3 * SZD;
        long oo   = OO   + (long)l * SZD;
        long ogu  = OGU  + (long)l * 2 * SZF;
        long odw  = ODW  + (long)l * SZF;

        rmsnorm_split<<<MM, 256>>>(x, wa + (long)l * DD, h, hhi, hlo);
        gemm2_kernel<false><<<dim3(24, 16), 512, GSM2>>>(hhi, hlo, wt + oqkv, scb + oqkv / 128, qkv, MM, 3 * DD, DD);
        attn_flash<<<dim3(SS / 64, BB * HH), 256, asmem>>>(qkv, h, alpha + (long)l * HH, ohi, olo);
        gemm2_kernel<true><<<dim3(8, 16), 512, GSM2>>>(ohi, olo, wt + oo, scb + oo / 128, x, MM, DD, DD);

        rmsnorm_split<<<MM, 256>>>(x, wm + (long)l * DD, nullptr, hhi, hlo);
        gemm2_kernel<false><<<dim3(64, 16), 512, GSM2>>>(hhi, hlo, wt + ogu, scb + ogu / 128, gu, MM, 2 * DFFN, DD);
        silumul_split<<<(long)MM * DFFN / 1024, 256>>>(gu, ghi, glo);
        gemm2_kernel<true><<<dim3(8, 16), 512, GSM2>>>(ghi, glo, wt + odw, scb + odw / 128, x, MM, DD, DFFN);
    }

    // final norm (fp16) + fp16 single-product head GEMM
    rmsnorm_h<<<MM, 256>>>(x, wf, hh);
    gemm1h_kernel<<<dim3(VV / 128, 16), 512, GSM1>>>(hh, wh, scb + OHD / 128, out, MM, VV, DD);
}

// round 15
// speedup vs baseline: 2.6005x; 1.1633x over previous
#include <cuda_runtime.h>
#include <cuda_bf16.h>
#include <cuda_fp16.h>
#include <cstdint>

using bf16 = __nv_bfloat16;

// ---------------- problem dims ----------------
#define BB   2
#define SS   1024
#define DD   1024
#define HH   16
#define DFFN 4096
#define LLAY 2
#define VV   32000
#define MM   (BB*SS)

// ---------------- ternary weight buffer (fp16, EXACT codes) ----------------
#define OQKV 0L
#define OO   (OQKV + (long)LLAY*3*DD*DD)
#define OGU  (OO   + (long)LLAY*DD*DD)
#define ODW  (OGU  + (long)LLAY*2*DFFN*DD)
#define OHD  (ODW  + (long)LLAY*DD*DFFN)
#define WTOT (OHD  + (long)VV*DD)

__device__ __half g_wh[WTOT];         // ternary codes as fp16 (exact)
__device__ float  g_sc[WTOT/128];     // per-group scales, packed: sc[n*Kg+g] at tensor offset/128
__device__ int    g_wtype;

// ---------------- activation scratch ----------------
__device__ float  g_x[MM*DD];
__device__ float  g_h[MM*DD];
__device__ float  g_qkv[(size_t)MM*3*DD];
__device__ float  g_gu[(size_t)MM*2*DFFN];
__device__ __half g_ha[(size_t)MM*DFFN];   // fp16 activations (max K = DFFN)

// ---------------- dtype probe ----------------
__global__ void probe_kernel(const void* raw) {
    if (threadIdx.x != 0) return;
    const unsigned* pw = (const unsigned*)raw;
    bool is_i32 = true;
    for (int i = 0; i < 256; i++) {
        unsigned w = pw[i];
        if (!(w == 0u || w == 1u || w == 0xFFFFFFFFu)) { is_i32 = false; break; }
    }
    if (is_i32) { g_wtype = 1; return; }
    bool is_f32 = true;
    for (int i = 0; i < 256; i++) {
        unsigned w = pw[i];
        if (!(w == 0u || w == 0x3F800000u || w == 0xBF800000u)) { is_f32 = false; break; }
    }
    if (is_f32) { g_wtype = 2; return; }
    const unsigned short* ph = (const unsigned short*)raw;
    bool is_b16 = true;
    for (int i = 0; i < 512; i++) {
        unsigned short w = ph[i];
        if (!(w == 0u || w == 0x3F80u || w == 0xBF80u)) { is_b16 = false; break; }
    }
    g_wtype = is_b16 ? 3 : 0;
}

__device__ __forceinline__ float load_tern(const void* p, long i, int t) {
    if (t == 1) return (float)((const int*)p)[i];
    if (t == 2) return ((const float*)p)[i];
    if (t == 3) return __bfloat162float(((const bf16*)p)[i]);
    return (float)((const int8_t*)p)[i];
}

// ---------------- weight convert: exact int -> fp16 ----------------
struct alignas(16) H8 { __half v[8]; };

__global__ void convert_th(const void* __restrict__ src, long srcOff, long dstOff, long n) {
    int t = g_wtype;
    if (t == 1) {
        long stride = (long)gridDim.x * blockDim.x * 8;
        for (long i = ((long)blockIdx.x * blockDim.x + threadIdx.x) * 8; i < n; i += stride) {
            const int4* p = (const int4*)((const int*)src + srcOff + i);
            int4 a = p[0], b = p[1];
            H8 o;
            o.v[0] = __float2half((float)a.x); o.v[1] = __float2half((float)a.y);
            o.v[2] = __float2half((float)a.z); o.v[3] = __float2half((float)a.w);
            o.v[4] = __float2half((float)b.x); o.v[5] = __float2half((float)b.y);
            o.v[6] = __float2half((float)b.z); o.v[7] = __float2half((float)b.w);
            *(H8*)(g_wh + dstOff + i) = o;
        }
    } else {
        long stride = (long)gridDim.x * blockDim.x;
        for (long i = (long)blockIdx.x * blockDim.x + threadIdx.x; i < n; i += stride)
            g_wh[dstOff + i] = __float2half(load_tern(src, srcOff + i, t));
    }
}

// ---------------- scale copy into packed layout ----------------
__global__ void copy_sc(const float* __restrict__ src, long srcOff, long dstOff, long n) {
    long stride = (long)gridDim.x * blockDim.x * 4;
    for (long i = ((long)blockIdx.x * blockDim.x + threadIdx.x) * 4; i < n; i += stride) {
        float4 v = *(const float4*)(src + srcOff + i);
        *(float4*)(g_sc + dstOff + i) = v;
    }
}

// ---------------- embedding ----------------
__global__ void embed_kernel(const int* __restrict__ ids, const void* __restrict__ et,
                             const float* __restrict__ es, float* __restrict__ x) {
    int t = g_wtype;
    int m = blockIdx.x;
    long base = (long)ids[m] * DD;
    for (int d = threadIdx.x; d < DD; d += blockDim.x) {
        long idx = base + d;
        x[(long)m * DD + d] = load_tern(et, idx, t) * es[idx >> 7];
    }
}

// ---------------- rmsnorm -> fp16 (optional f32 copy for attn residual) ----------------
__global__ void rmsnorm_h(const float* __restrict__ x, const float* __restrict__ w,
                          float* __restrict__ hout, __half* __restrict__ hq) {
    int m = blockIdx.x;
    const float* xr = x + (long)m * DD;
    float ss = 0.f;
    for (int d = threadIdx.x; d < DD; d += blockDim.x) { float v = xr[d]; ss += v * v; }
    __shared__ float red[256];
    red[threadIdx.x] = ss; __syncthreads();
    #pragma unroll
    for (int st = 128; st > 0; st >>= 1) {
        if (threadIdx.x < st) red[threadIdx.x] += red[threadIdx.x + st];
        __syncthreads();
    }
    float r = rsqrtf(red[0] * (1.0f / DD) + 1e-6f);
    for (int d = threadIdx.x; d < DD; d += blockDim.x) {
        long i = (long)m * DD + d;
        float y = xr[d] * r * w[d];
        if (hout) hout[i] = y;
        hq[i] = __float2half(y);
    }
}

// ---------------- mma.sync helpers ----------------
__device__ __forceinline__ void cpa16(uint32_t d, const void* s) {
    asm volatile("cp.async.ca.shared.global [%0], [%1], 16;\n" :: "r"(d), "l"(s));
}
__device__ __forceinline__ void ldsm4(uint32_t* r, uint32_t a) {
    asm volatile("ldmatrix.sync.aligned.m8n8.x4.shared.b16 {%0,%1,%2,%3},[%4];"
                 : "=r"(r[0]), "=r"(r[1]), "=r"(r[2]), "=r"(r[3]) : "r"(a));
}
__device__ __forceinline__ void ldsm2(uint32_t* r, uint32_t a) {
    asm volatile("ldmatrix.sync.aligned.m8n8.x2.shared.b16 {%0,%1},[%2];"
                 : "=r"(r[0]), "=r"(r[1]) : "r"(a));
}
__device__ __forceinline__ void mma16816h(float* c, const uint32_t* a, const uint32_t* b) {
    asm volatile("mma.sync.aligned.m16n8k16.row.col.f32.f16.f16.f32 "
                 "{%0,%1,%2,%3},{%4,%5,%6,%7},{%8,%9},{%0,%1,%2,%3};"
                 : "+f"(c[0]), "+f"(c[1]), "+f"(c[2]), "+f"(c[3])
                 : "r"(a[0]), "r"(a[1]), "r"(a[2]), "r"(a[3]), "r"(b[0]), "r"(b[1]));
}

// ---------------- 1-product group-scaled GEMM (fp16) ----------------
// C[M,N] (+)= sum_g s[n,g] * sum_{k in g} A[m,k] * T[n,k]
// BM=BN=128, BK=32, 512 threads (16 warps as 4x4, warp tile 32x32), 4-stage cp.async.
#define STG1_B 20480
#define NSTG   4
#define GSM1   (NSTG*STG1_B)

template<bool ACCF>
__global__ __launch_bounds__(512, 1)
void gemm1h(const __half* __restrict__ Ah, const __half* __restrict__ T,
            const float* __restrict__ sc, float* __restrict__ C,
            int M, int N, int K) {
    extern __shared__ char smem_raw[];
    const uint32_t sbase = (uint32_t)__cvta_generic_to_shared(smem_raw);
    const int tid = threadIdx.x, lane = tid & 31, wid = tid >> 5;
    const int wm = wid >> 2, wn = wid & 3;
    const int bm = blockIdx.y * 128, bn = blockIdx.x * 128;
    const int Kg = K >> 7;
    const int r0 = tid >> 2, cc = (tid & 3) * 8;

    int aoffE[2], boffE[4];
    {
        int r = lane & 15, kh = (lane >> 4) * 8;
        #pragma unroll
        for (int mi = 0; mi < 2; mi++) aoffE[mi] = (wm * 32 + mi * 16 + r) * 40 + kh;
        #pragma unroll
        for (int ni = 0; ni < 4; ni++) boffE[ni] = (wn * 32 + ni * 8 + (r & 7)) * 40 + ((r >> 3) * 8);
    }

    float accM[2][4][4], accP[2][4][4];
    #pragma unroll
    for (int i = 0; i < 2; i++)
        #pragma unroll
        for (int j = 0; j < 4; j++)
            #pragma unroll
            for (int c = 0; c < 4; c++) { accM[i][j][c] = 0.f; accP[i][j][c] = 0.f; }

    auto load_stage = [&](int kt) {
        uint32_t sb = sbase + (kt & (NSTG - 1)) * STG1_B;
        uint32_t d = r0 * 80 + cc * 2;
        size_t ga = (size_t)(bm + r0) * K + (size_t)kt * 32 + cc;
        size_t gb = (size_t)(bn + r0) * K + (size_t)kt * 32 + cc;
        cpa16(sb + d,         Ah + ga);
        cpa16(sb + 10240 + d, T + gb);
    };

    const int KT = K >> 5;
    load_stage(0); asm volatile("cp.async.commit_group;\n" ::: "memory");
    load_stage(1); asm volatile("cp.async.commit_group;\n" ::: "memory");
    load_stage(2); asm volatile("cp.async.commit_group;\n" ::: "memory");

    for (int kt = 0; kt < KT; kt++) {
        asm volatile("cp.async.wait_group 2;\n" ::: "memory");
        __syncthreads();
        if (kt + 3 < KT) load_stage(kt + 3);
        asm volatile("cp.async.commit_group;\n" ::: "memory");

        uint32_t sb = sbase + (kt & (NSTG - 1)) * STG1_B;
        #pragma unroll
        for (int kk = 0; kk < 2; kk++) {
            const int kb = kk * 32;
            uint32_t a[2][4], b[4][2];
            #pragma unroll
            for (int ni = 0; ni < 4; ni++) ldsm2(b[ni], sb + 10240 + boffE[ni] * 2 + kb);
            #pragma unroll
            for (int mi = 0; mi < 2; mi++) ldsm4(a[mi], sb + aoffE[mi] * 2 + kb);
            #pragma unroll
            for (int mi = 0; mi < 2; mi++)
                #pragma unroll
                for (int ni = 0; ni < 4; ni++) mma16816h(accP[mi][ni], a[mi], b[ni]);
        }

        if ((kt & 3) == 3) {
            int g = kt >> 2;
            #pragma unroll
            for (int ni = 0; ni < 4; ni++) {
                int col = bn + wn * 32 + ni * 8 + (lane & 3) * 2;
                float s0 = __ldg(sc + (size_t)col * Kg + g);
                float s1 = __ldg(sc + (size_t)(col + 1) * Kg + g);
                #pragma unroll
                for (int mi = 0; mi < 2; mi++) {
                    accM[mi][ni][0] += s0 * accP[mi][ni][0];
                    accM[mi][ni][1] += s1 * accP[mi][ni][1];
                    accM[mi][ni][2] += s0 * accP[mi][ni][2];
                    accM[mi][ni][3] += s1 * accP[mi][ni][3];
                    accP[mi][ni][0] = 0.f; accP[mi][ni][1] = 0.f;
                    accP[mi][ni][2] = 0.f; accP[mi][ni][3] = 0.f;
                }
            }
        }
    }

    #pragma unroll
    for (int mi = 0; mi < 2; mi++) {
        int row = bm + wm * 32 + mi * 16 + (lane >> 2);
        #pragma unroll
        for (int ni = 0; ni < 4; ni++) {
            int col = bn + wn * 32 + ni * 8 + (lane & 3) * 2;
            float* p0 = C + (size_t)row * N + col;
            float* p1 = p0 + (size_t)8 * N;
            if (ACCF) {
                p0[0] += accM[mi][ni][0]; p0[1] += accM[mi][ni][1];
                p1[0] += accM[mi][ni][2]; p1[1] += accM[mi][ni][3];
            } else {
                p0[0] = accM[mi][ni][0]; p0[1] = accM[mi][ni][1];
                p1[0] = accM[mi][ni][2]; p1[1] = accM[mi][ni][3];
            }
        }
    }
}

// ---------------- flash-style tiled causal attention (fp16 out) ----------------
__device__ __forceinline__ float rmax16(float v) {
    #pragma unroll
    for (int m = 1; m < 16; m <<= 1) v = fmaxf(v, __shfl_xor_sync(0xffffffffu, v, m));
    return v;
}
__device__ __forceinline__ float rsum16(float v) {
    #pragma unroll
    for (int m = 1; m < 16; m <<= 1) v += __shfl_xor_sync(0xffffffffu, v, m);
    return v;
}

__global__ __launch_bounds__(256)
void attn_flash(const float* __restrict__ qkv, const float* __restrict__ h,
                const float* __restrict__ alpha, __half* __restrict__ oq) {
    extern __shared__ float sm[];
    float (*Qs)[65] = (float(*)[65])sm;
    float (*Ks)[65] = (float(*)[65])(sm + 64 * 65);
    float (*Vs)[65] = (float(*)[65])(sm + 2 * 64 * 65);
    float (*Ps)[65] = (float(*)[65])(sm + 3 * 64 * 65);

    int qt = blockIdx.x;
    int bh = blockIdx.y;
    int b = bh >> 4, hh = bh & 15;
    int tid = threadIdx.x;
    int tx = tid & 15, ty = tid >> 4;

    const float* qb = qkv + (size_t)(b * SS + qt * 64) * 3072 + hh * 64;
    for (int i = tid; i < 64 * 64; i += 256)
        Qs[i >> 6][i & 63] = qb[(size_t)(i >> 6) * 3072 + (i & 63)];

    float m_run[4], l_run[4], O[4][4];
    #pragma unroll
    for (int i = 0; i < 4; i++) {
        m_run[i] = -3.4e38f; l_run[i] = 0.f;
        O[i][0] = O[i][1] = O[i][2] = O[i][3] = 0.f;
    }

    const float* kb = qkv + (size_t)b * SS * 3072 + 1024 + hh * 64;
    const float* vb = qkv + (size_t)b * SS * 3072 + 2048 + hh * 64;

    for (int kt = 0; kt <= qt; kt++) {
        __syncthreads();
        for (int i = tid; i < 64 * 64; i += 256) {
            int r = i >> 6, c = i & 63;
            size_t gr = (size_t)(kt * 64 + r) * 3072 + c;
            Ks[r][c] = kb[gr];
            Vs[r][c] = vb[gr];
        }
        __syncthreads();

        float s[4][4];
        #pragma unroll
        for (int i = 0; i < 4; i++) { s[i][0]=0.f; s[i][1]=0.f; s[i][2]=0.f; s[i][3]=0.f; }
        #pragma unroll 8
        for (int d = 0; d < 64; d++) {
            float a[4], bv[4];
            #pragma unroll
            for (int i = 0; i < 4; i++) a[i]  = Qs[ty * 4 + i][d];
            #pragma unroll
            for (int j = 0; j < 4; j++) bv[j] = Ks[tx * 4 + j][d];
            #pragma unroll
            for (int i = 0; i < 4; i++)
                #pragma unroll
                for (int j = 0; j < 4; j++) s[i][j] += a[i] * bv[j];
        }
        if (kt == qt) {
            #pragma unroll
            for (int i = 0; i < 4; i++) {
                int row = ty * 4 + i;
                #pragma unroll
                for (int j = 0; j < 4; j++)
                    if (tx * 4 + j > row) s[i][j] = -3.4e38f;
        } }
        #pragma unroll
        for (int i = 0; i < 4; i++) {
            float tm = fmaxf(fmaxf(s[i][0] * 0.125f, s[i][1] * 0.125f),
                             fmaxf(s[i][2] * 0.125f, s[i][3] * 0.125f));
            tm = rmax16(tm);
            float m_new = fmaxf(m_run[i], tm);
            float fac = expf(m_run[i] - m_new);
            float rs = 0.f;
            #pragma unroll
            for (int j = 0; j < 4; j++) {
                float p = expf(s[i][j] * 0.125f - m_new);
                Ps[ty * 4 + i][tx * 4 + j] = p;
                rs += p;
            }
            rs = rsum16(rs);
            l_run[i] = l_run[i] * fac + rs;
            m_run[i] = m_new;
            #pragma unroll
            for (int j = 0; j < 4; j++) O[i][j] *= fac;
        }
        __syncthreads();

        #pragma unroll 8
        for (int t = 0; t < 64; t++) {
            float a[4], bv[4];
            #pragma unroll
            for (int i = 0; i < 4; i++) a[i]  = Ps[ty * 4 + i][t];
            #pragma unroll
            for (int j = 0; j < 4; j++) bv[j] = Vs[t][tx * 4 + j];
            #pragma unroll
            for (int i = 0; i < 4; i++)
                #pragma unroll
                for (int j = 0; j < 4; j++) O[i][j] += a[i] * bv[j];
        }
    }

    float ah = alpha[hh];
    #pragma unroll
    for (int i = 0; i < 4; i++) {
        float inv = 1.f / l_run[i];
        int row = qt * 64 + ty * 4 + i;
        #pragma unroll
        for (int j = 0; j < 4; j++) {
            long idx = (long)(b * SS + row) * DD + hh * 64 + tx * 4 + j;
            oq[idx] = __float2half(O[i][j] * inv + ah * h[idx]);
        }
    }
}

// ---------------- silu(g)*u -> fp16 (vectorized x4) ----------------
struct alignas(8) Hx4 { __half v[4]; };
__global__ void silumul_h(const float* __restrict__ gu, __half* __restrict__ ha) {
    long i = ((long)blockIdx.x * 256 + threadIdx.x) * 4;
    long m = i >> 12, j = i & 4095;
    float4 a4 = *(const float4*)(gu + (m << 13) + j);
    float4 u4 = *(const float4*)(gu + (m << 13) + 4096 + j);
    float av[4] = {a4.x, a4.y, a4.z, a4.w};
    float uv[4] = {u4.x, u4.y, u4.z, u4.w};
    Hx4 o;
    #pragma unroll
    for (int c = 0; c < 4; c++) {
        float val = av[c] / (1.f + expf(-av[c])) * uv[c];
        o.v[c] = __float2half(val);
    }
    *(Hx4*)(ha + i) = o;
}

// ---------------- host launcher ----------------
extern "C" void kernel_launch(void* const* d_in, const int* in_sizes, int n_in,
                              void* d_out, int out_size) {
    (void)in_sizes; (void)n_in; (void)out_size;
    const int*   ids   = (const int*)  d_in[0];
    const void*  emb_t = d_in[1];
    const float* emb_s = (const float*)d_in[2];
    const void*  qt = d_in[3];  const float* qs = (const float*)d_in[4];
    const void*  kt = d_in[5];  const float* ks = (const float*)d_in[6];
    const void*  vt = d_in[7];  const float* vs = (const float*)d_in[8];
    const void*  ot = d_in[9];  const float* os = (const float*)d_in[10];
    const void*  gt = d_in[11]; const float* gs = (const float*)d_in[12];
    const void*  ut = d_in[13]; const float* us = (const float*)d_in[14];
    const void*  dt = d_in[15]; const float* ds = (const float*)d_in[16];
    const float* wa    = (const float*)d_in[17];
    const float* wm    = (const float*)d_in[18];
    const float* alpha = (const float*)d_in[19];
    const float* wf    = (const float*)d_in[20];
    const void*  ht = d_in[21]; const float* hs = (const float*)d_in[22];
    float* out = (float*)d_out;

    float *x, *h, *qkv, *gu, *scb;
    __half *wh, *ha;
    cudaGetSymbolAddress((void**)&x,   g_x);
    cudaGetSymbolAddress((void**)&h,   g_h);
    cudaGetSymbolAddress((void**)&qkv, g_qkv);
    cudaGetSymbolAddress((void**)&gu,  g_gu);
    cudaGetSymbolAddress((void**)&wh,  g_wh);
    cudaGetSymbolAddress((void**)&scb, g_sc);
    cudaGetSymbolAddress((void**)&ha,  g_ha);

    cudaFuncSetAttribute(gemm1h<false>, cudaFuncAttributeMaxDynamicSharedMemorySize, GSM1);
    cudaFuncSetAttribute(gemm1h<true>,  cudaFuncAttributeMaxDynamicSharedMemorySize, GSM1);
    cudaFuncSetAttribute(attn_flash, cudaFuncAttributeMaxDynamicSharedMemorySize, 4 * 64 * 65 * 4);

    probe_kernel<<<1, 32>>>(emb_t);

    const long SZD = (long)DD * DD;       // 1,048,576
    const long SZF = (long)DFFN * DD;     // 4,194,304
    const long ngD = SZD / 128, ngF = SZF / 128;

    // weights -> exact fp16 codes
    for (int l = 0; l < LLAY; l++) {
        convert_th<<<1024, 256>>>(qt, l * SZD, OQKV + (long)l * 3 * SZD,           SZD);
        convert_th<<<1024, 256>>>(kt, l * SZD, OQKV + (long)l * 3 * SZD + SZD,     SZD);
        convert_th<<<1024, 256>>>(vt, l * SZD, OQKV + (long)l * 3 * SZD + 2 * SZD, SZD);
        convert_th<<<1024, 256>>>(gt, l * SZF, OGU  + (long)l * 2 * SZF,           SZF);
        convert_th<<<1024, 256>>>(ut, l * SZF, OGU  + (long)l * 2 * SZF + SZF,     SZF);
    }
    convert_th<<<1024, 256>>>(ot, 0, OO,  (long)LLAY * SZD);
    convert_th<<<1024, 256>>>(dt, 0, ODW, (long)LLAY * SZF);
    convert_th<<<2048, 256>>>(ht, 0, OHD, (long)VV * DD);

    // scales -> packed layout matching weight offsets
    for (int l = 0; l < LLAY; l++) {
        copy_sc<<<64, 256>>>(qs, l * ngD, (OQKV + (long)l * 3 * SZD) / 128,           ngD);
        copy_sc<<<64, 256>>>(ks, l * ngD, (OQKV + (long)l * 3 * SZD + SZD) / 128,     ngD);
        copy_sc<<<64, 256>>>(vs, l * ngD, (OQKV + (long)l * 3 * SZD + 2 * SZD) / 128, ngD);
        copy_sc<<<64, 256>>>(gs, l * ngF, (OGU + (long)l * 2 * SZF) / 128,            ngF);
        copy_sc<<<64, 256>>>(us, l * ngF, (OGU + (long)l * 2 * SZF + SZF) / 128,      ngF);
    }
    copy_sc<<<64, 256>>>(os, 0, OO / 128,  (long)LLAY * ngD);
    copy_sc<<<128, 256>>>(ds, 0, ODW / 128, (long)LLAY * ngF);
    copy_sc<<<256, 256>>>(hs, 0, OHD / 128, (long)VV * DD / 128);

    embed_kernel<<<MM, 256>>>(ids, emb_t, emb_s, x);

    const size_t asmem = 4 * 64 * 65 * 4;

    for (int l = 0; l < LLAY; l++) {
        long oqkv = OQKV + (long)l * 3 * SZD;
        long oo   = OO   + (long)l * SZD;
        long ogu  = OGU  + (long)l * 2 * SZF;
        long odw  = ODW  + (long)l * SZF;

        rmsnorm_h<<<MM, 256>>>(x, wa + (long)l * DD, h, ha);
        gemm1h<false><<<dim3(24, 16), 512, GSM1>>>(ha, wh + oqkv, scb + oqkv / 128, qkv, MM, 3 * DD, DD);
        attn_flash<<<dim3(SS / 64, BB * HH), 256, asmem>>>(qkv, h, alpha + (long)l * HH, ha);
        gemm1h<true><<<dim3(8, 16), 512, GSM1>>>(ha, wh + oo, scb + oo / 128, x, MM, DD, DD);

        rmsnorm_h<<<MM, 256>>>(x, wm + (long)l * DD, nullptr, ha);
        gemm1h<false><<<dim3(64, 16), 512, GSM1>>>(ha, wh + ogu, scb + ogu / 128, gu, MM, 2 * DFFN, DD);
        silumul_h<<<(long)MM * DFFN / 1024, 256>>>(gu, ha);
        gemm1h<true><<<dim3(8, 16), 512, GSM1>>>(ha, wh + odw, scb + odw / 128, x, MM, DD, DFFN);
    }

    // final norm + head
    rmsnorm_h<<<MM, 256>>>(x, wf, nullptr, ha);
    gemm1h<false><<<dim3(VV / 128, 16), 512, GSM1>>>(ha, wh + OHD, scb + OHD / 128, out, MM, VV, DD);
}

// round 16
// speedup vs baseline: 2.8076x; 1.0796x over previous
#include <cuda_runtime.h>
#include <cuda_bf16.h>
#include <cuda_fp16.h>
#include <cstdint>

using bf16 = __nv_bfloat16;

// ---------------- problem dims ----------------
#define BB   2
#define SS   1024
#define DD   1024
#define HH   16
#define DFFN 4096
#define LLAY 2
#define VV   32000
#define MM   (BB*SS)

// ---------------- ternary weight buffer (fp16, EXACT codes) ----------------
#define OQKV 0L
#define OO   (OQKV + (long)LLAY*3*DD*DD)
#define OGU  (OO   + (long)LLAY*DD*DD)
#define ODW  (OGU  + (long)LLAY*2*DFFN*DD)
#define OHD  (ODW  + (long)LLAY*DD*DFFN)
#define WTOT (OHD  + (long)VV*DD)

__device__ __half g_wh[WTOT];         // ternary codes as fp16 (exact)
__device__ float  g_sc[WTOT/128];     // per-group scales, packed: sc[n*Kg+g] at tensor offset/128
__device__ int    g_wtype;

// ---------------- activation scratch ----------------
__device__ float  g_x[MM*DD];
__device__ float  g_h[MM*DD];
__device__ float  g_qkv[(size_t)MM*3*DD];
__device__ float  g_gu[(size_t)MM*2*DFFN];
__device__ __half g_ha[(size_t)MM*DFFN];   // fp16 activations (max K = DFFN)

// ---------------- dtype probe ----------------
__global__ void probe_kernel(const void* raw) {
    if (threadIdx.x != 0) return;
    const unsigned* pw = (const unsigned*)raw;
    bool is_i32 = true;
    for (int i = 0; i < 256; i++) {
        unsigned w = pw[i];
        if (!(w == 0u || w == 1u || w == 0xFFFFFFFFu)) { is_i32 = false; break; }
    }
    if (is_i32) { g_wtype = 1; return; }
    bool is_f32 = true;
    for (int i = 0; i < 256; i++) {
        unsigned w = pw[i];
        if (!(w == 0u || w == 0x3F800000u || w == 0xBF800000u)) { is_f32 = false; break; }
    }
    if (is_f32) { g_wtype = 2; return; }
    const unsigned short* ph = (const unsigned short*)raw;
    bool is_b16 = true;
    for (int i = 0; i < 512; i++) {
        unsigned short w = ph[i];
        if (!(w == 0u || w == 0x3F80u || w == 0xBF80u)) { is_b16 = false; break; }
    }
    g_wtype = is_b16 ? 3 : 0;
}

__device__ __forceinline__ float load_tern(const void* p, long i, int t) {
    if (t == 1) return (float)((const int*)p)[i];
    if (t == 2) return ((const float*)p)[i];
    if (t == 3) return __bfloat162float(((const bf16*)p)[i]);
    return (float)((const int8_t*)p)[i];
}

// ---------------- batched weight convert: 13 tensors in one launch ----------------
#define NCVT 13
struct CvtArgs {
    const void* src[NCVT];
    long srcOff[NCVT];
    long dstOff[NCVT];
    long n[NCVT];
};
struct alignas(16) H8 { __half v[8]; };

__global__ void convert_all(CvtArgs a) {
    int s = blockIdx.y;
    int t = g_wtype;
    const void* src = a.src[s];
    long srcOff = a.srcOff[s], dstOff = a.dstOff[s], n = a.n[s];
    if (t == 1) {
        long stride = (long)gridDim.x * blockDim.x * 8;
        for (long i = ((long)blockIdx.x * blockDim.x + threadIdx.x) * 8; i < n; i += stride) {
            const int4* p = (const int4*)((const int*)src + srcOff + i);
            int4 q = p[0], r = p[1];
            H8 o;
            o.v[0] = __float2half((float)q.x); o.v[1] = __float2half((float)q.y);
            o.v[2] = __float2half((float)q.z); o.v[3] = __float2half((float)q.w);
            o.v[4] = __float2half((float)r.x); o.v[5] = __float2half((float)r.y);
            o.v[6] = __float2half((float)r.z); o.v[7] = __float2half((float)r.w);
            *(H8*)(g_wh + dstOff + i) = o;
        }
    } else {
        long stride = (long)gridDim.x * blockDim.x;
        for (long i = (long)blockIdx.x * blockDim.x + threadIdx.x; i < n; i += stride)
            g_wh[dstOff + i] = __float2half(load_tern(src, srcOff + i, t));
    }
}

// ---------------- batched scale copy: 13 tensors in one launch ----------------
struct ScArgs {
    const float* src[NCVT];
    long srcOff[NCVT];
    long dstOff[NCVT];
    long n[NCVT];
};
__global__ void copy_sc_all(ScArgs a) {
    int s = blockIdx.y;
    const float* src = a.src[s];
    long srcOff = a.srcOff[s], dstOff = a.dstOff[s], n = a.n[s];
    long stride = (long)gridDim.x * blockDim.x * 4;
    for (long i = ((long)blockIdx.x * blockDim.x + threadIdx.x) * 4; i < n; i += stride) {
        float4 v = *(const float4*)(src + srcOff + i);
        *(float4*)(g_sc + dstOff + i) = v;
    }
}

// ---------------- embedding ----------------
__global__ void embed_kernel(const int* __restrict__ ids, const void* __restrict__ et,
                             const float* __restrict__ es, float* __restrict__ x) {
    int t = g_wtype;
    int m = blockIdx.x;
    long base = (long)ids[m] * DD;
    for (int d = threadIdx.x; d < DD; d += blockDim.x) {
        long idx = base + d;
        x[(long)m * DD + d] = load_tern(et, idx, t) * es[idx >> 7];
    }
}

// ---------------- rmsnorm -> fp16 (optional f32 copy for attn residual) ----------------
__global__ void rmsnorm_h(const float* __restrict__ x, const float* __restrict__ w,
                          float* __restrict__ hout, __half* __restrict__ hq) {
    int m = blockIdx.x;
    const float* xr = x + (long)m * DD;
    float ss = 0.f;
    for (int d = threadIdx.x; d < DD; d += blockDim.x) { float v = xr[d]; ss += v * v; }
    __shared__ float red[256];
    red[threadIdx.x] = ss; __syncthreads();
    #pragma unroll
    for (int st = 128; st > 0; st >>= 1) {
        if (threadIdx.x < st) red[threadIdx.x] += red[threadIdx.x + st];
        __syncthreads();
    }
    float r = rsqrtf(red[0] * (1.0f / DD) + 1e-6f);
    for (int d = threadIdx.x; d < DD; d += blockDim.x) {
        long i = (long)m * DD + d;
        float y = xr[d] * r * w[d];
        if (hout) hout[i] = y;
        hq[i] = __float2half(y);
    }
}

// ---------------- mma.sync helpers ----------------
__device__ __forceinline__ void cpa16(uint32_t d, const void* s) {
    asm volatile("cp.async.ca.shared.global [%0], [%1], 16;\n" :: "r"(d), "l"(s));
}
__device__ __forceinline__ void ldsm4(uint32_t* r, uint32_t a) {
    asm volatile("ldmatrix.sync.aligned.m8n8.x4.shared.b16 {%0,%1,%2,%3},[%4];"
                 : "=r"(r[0]), "=r"(r[1]), "=r"(r[2]), "=r"(r[3]) : "r"(a));
}
__device__ __forceinline__ void ldsm2(uint32_t* r, uint32_t a) {
    asm volatile("ldmatrix.sync.aligned.m8n8.x2.shared.b16 {%0,%1},[%2];"
                 : "=r"(r[0]), "=r"(r[1]) : "r"(a));
}
__device__ __forceinline__ void mma16816h(float* c, const uint32_t* a, const uint32_t* b) {
    asm volatile("mma.sync.aligned.m16n8k16.row.col.f32.f16.f16.f32 "
                 "{%0,%1,%2,%3},{%4,%5,%6,%7},{%8,%9},{%0,%1,%2,%3};"
                 : "+f"(c[0]), "+f"(c[1]), "+f"(c[2]), "+f"(c[3])
                 : "r"(a[0]), "r"(a[1]), "r"(a[2]), "r"(a[3]), "r"(b[0]), "r"(b[1]));
}

// ---------------- 1-product group-scaled GEMM (fp16), BK=64 stages ----------------
// C[M,N] (+)= sum_g s[n,g] * sum_{k in g} A[m,k] * T[n,k]
// BM=BN=128, BK=64, 512 threads (16 warps as 4x4, warp tile 32x32), 3-stage cp.async.
// Stage: A0|A1|B0|B1, each 128 rows x 32 cols fp16, row stride 40 elems (10240 B each).
#define STGB 40960
#define NSTG 3
#define GSM1 (NSTG*STGB)

template<bool ACCF>
__global__ __launch_bounds__(512, 1)
void gemm1h(const __half* __restrict__ Ah, const __half* __restrict__ T,
            const float* __restrict__ sc, float* __restrict__ C,
            int M, int N, int K) {
    extern __shared__ char smem_raw[];
    const uint32_t sbase = (uint32_t)__cvta_generic_to_shared(smem_raw);
    const int tid = threadIdx.x, lane = tid & 31, wid = tid >> 5;
    const int wm = wid >> 2, wn = wid & 3;
    const int bm = blockIdx.y * 128, bn = blockIdx.x * 128;
    const int Kg = K >> 7;
    const int r0 = tid >> 2, cc = (tid & 3) * 8;

    int aoffE[2], boffE[4];
    {
        int r = lane & 15, kh = (lane >> 4) * 8;
        #pragma unroll
        for (int mi = 0; mi < 2; mi++) aoffE[mi] = (wm * 32 + mi * 16 + r) * 40 + kh;
        #pragma unroll
        for (int ni = 0; ni < 4; ni++) boffE[ni] = (wn * 32 + ni * 8 + (r & 7)) * 40 + ((r >> 3) * 8);
    }

    float accM[2][4][4], accP[2][4][4];
    #pragma unroll
    for (int i = 0; i < 2; i++)
        #pragma unroll
        for (int j = 0; j < 4; j++)
            #pragma unroll
            for (int c = 0; c < 4; c++) { accM[i][j][c] = 0.f; accP[i][j][c] = 0.f; }

    auto load_stage = [&](int kt, int st) {
        uint32_t sb = sbase + st * STGB;
        uint32_t d = r0 * 80 + cc * 2;
        #pragma unroll
        for (int j = 0; j < 2; j++) {
            size_t ga = (size_t)(bm + r0) * K + (size_t)kt * 64 + j * 32 + cc;
            size_t gb = (size_t)(bn + r0) * K + (size_t)kt * 64 + j * 32 + cc;
            cpa16(sb + j * 10240 + d,         Ah + ga);
            cpa16(sb + 20480 + j * 10240 + d, T + gb);
        }
    };

    const int KT = K >> 6;
    load_stage(0, 0); asm volatile("cp.async.commit_group;\n" ::: "memory");
    load_stage(1, 1); asm volatile("cp.async.commit_group;\n" ::: "memory");

    int st = 0;
    for (int kt = 0; kt < KT; kt++) {
        asm volatile("cp.async.wait_group 1;\n" ::: "memory");
        __syncthreads();
        if (kt + 2 < KT) {
            int ldst = st + 2; if (ldst >= NSTG) ldst -= NSTG;
            load_stage(kt + 2, ldst);
        }
        asm volatile("cp.async.commit_group;\n" ::: "memory");

        uint32_t sb = sbase + st * STGB;
        #pragma unroll
        for (int kk = 0; kk < 4; kk++) {
            const uint32_t cb = (kk >> 1) * 10240 + (kk & 1) * 32;
            uint32_t a[2][4], b[4][2];
            #pragma unroll
            for (int ni = 0; ni < 4; ni++) ldsm2(b[ni], sb + 20480 + cb + boffE[ni] * 2);
            #pragma unroll
            for (int mi = 0; mi < 2; mi++) ldsm4(a[mi], sb + cb + aoffE[mi] * 2);
            #pragma unroll
            for (int mi = 0; mi < 2; mi++)
                #pragma unroll
                for (int ni = 0; ni < 4; ni++) mma16816h(accP[mi][ni], a[mi], b[ni]);
        }

        if (kt & 1) {     // 128-K group boundary: fold with fp32 scales
            int g = kt >> 1;
            #pragma unroll
            for (int ni = 0; ni < 4; ni++) {
                int col = bn + wn * 32 + ni * 8 + (lane & 3) * 2;
                float s0 = __ldg(sc + (size_t)col * Kg + g);
                float s1 = __ldg(sc + (size_t)(col + 1) * Kg + g);
                #pragma unroll
                for (int mi = 0; mi < 2; mi++) {
                    accM[mi][ni][0] += s0 * accP[mi][ni][0];
                    accM[mi][ni][1] += s1 * accP[mi][ni][1];
                    accM[mi][ni][2] += s0 * accP[mi][ni][2];
                    accM[mi][ni][3] += s1 * accP[mi][ni][3];
                    accP[mi][ni][0] = 0.f; accP[mi][ni][1] = 0.f;
                    accP[mi][ni][2] = 0.f; accP[mi][ni][3] = 0.f;
                }
            }
        }
        if (++st == NSTG) st = 0;
    }

    #pragma unroll
    for (int mi = 0; mi < 2; mi++) {
        int row = bm + wm * 32 + mi * 16 + (lane >> 2);
        #pragma unroll
        for (int ni = 0; ni < 4; ni++) {
            int col = bn + wn * 32 + ni * 8 + (lane & 3) * 2;
            float* p0 = C + (size_t)row * N + col;
            float* p1 = p0 + (size_t)8 * N;
            if (ACCF) {
                p0[0] += accM[mi][ni][0]; p0[1] += accM[mi][ni][1];
                p1[0] += accM[mi][ni][2]; p1[1] += accM[mi][ni][3];
            } else {
                p0[0] = accM[mi][ni][0]; p0[1] = accM[mi][ni][1];
                p1[0] = accM[mi][ni][2]; p1[1] = accM[mi][ni][3];
            }
        }
    }
}

// ---------------- flash-style tiled causal attention (fp16 out) ----------------
__device__ __forceinline__ float rmax16(float v) {
    #pragma unroll
    for (int m = 1; m < 16; m <<= 1) v = fmaxf(v, __shfl_xor_sync(0xffffffffu, v, m));
    return v;
}
__device__ __forceinline__ float rsum16(float v) {
    #pragma unroll
    for (int m = 1; m < 16; m <<= 1) v += __shfl_xor_sync(0xffffffffu, v, m);
    return v;
}

__global__ __launch_bounds__(256)
void attn_flash(const float* __restrict__ qkv, const float* __restrict__ h,
                const float* __restrict__ alpha, __half* __restrict__ oq) {
    extern __shared__ float sm[];
    float (*Qs)[65] = (float(*)[65])sm;
    float (*Ks)[65] = (float(*)[65])(sm + 64 * 65);
    float (*Vs)[65] = (float(*)[65])(sm + 2 * 64 * 65);
    float (*Ps)[65] = (float(*)[65])(sm + 3 * 64 * 65);

    int qt = blockIdx.x;
    int bh = blockIdx.y;
    int b = bh >> 4, hh = bh & 15;
    int tid = threadIdx.x;
    int tx = tid & 15, ty = tid >> 4;

    const float* qb = qkv + (size_t)(b * SS + qt * 64) * 3072 + hh * 64;
    for (int i = tid; i < 64 * 64; i += 256)
        Qs[i >> 6][i & 63] = qb[(size_t)(i >> 6) * 3072 + (i & 63)];

    float m_run[4], l_run[4], O[4][4];
    #pragma unroll
    for (int i = 0; i < 4; i++) {
        m_run[i] = -3.4e38f; l_run[i] = 0.f;
        O[i][0] = O[i][1] = O[i][2] = O[i][3] = 0.f;
    }

    const float* kb = qkv + (size_t)b * SS * 3072 + 1024 + hh * 64;
    const float* vb = qkv + (size_t)b * SS * 3072 + 2048 + hh * 64;

    for (int kt = 0; kt <= qt; kt++) {
        __syncthreads();
        for (int i = tid; i < 64 * 64; i += 256) {
            int r = i >> 6, c = i & 63;
            size_t gr = (size_t)(kt * 64 + r) * 3072 + c;
            Ks[r][c] = kb[gr];
            Vs[r][c] = vb[gr];
        }
        __syncthreads();

        float s[4][4];
        #pragma unroll
        for (int i = 0; i < 4; i++) { s[i][0]=0.f; s[i][1]=0.f; s[i][2]=0.f; s[i][3]=0.f; }
        #pragma unroll 8
        for (int d = 0; d < 64; d++) {
            float a[4], bv[4];
            #pragma unroll
            for (int i = 0; i < 4; i++) a[i]  = Qs[ty * 4 + i][d];
            #pragma unroll
            for (int j = 0; j < 4; j++) bv[j] = Ks[tx * 4 + j][d];
            #pragma unroll
            for (int i = 0; i < 4; i++)
                #pragma unroll
                for (int j = 0; j < 4; j++) s[i][j] += a[i] * bv[j];
        }
        if (kt == qt) {
            #pragma unroll
            for (int i = 0; i < 4; i++) {
                int row = ty * 4 + i;
                #pragma unroll
                for (int j = 0; j < 4; j++)
                    if (tx * 4 + j > row) s[i][j] = -3.4e38f;
        } }
        #pragma unroll
        for (int i = 0; i < 4; i++) {
            float tm = fmaxf(fmaxf(s[i][0] * 0.125f, s[i][1] * 0.125f),
                             fmaxf(s[i][2] * 0.125f, s[i][3] * 0.125f));
            tm = rmax16(tm);
            float m_new = fmaxf(m_run[i], tm);
            float fac = expf(m_run[i] - m_new);
            float rs = 0.f;
            #pragma unroll
            for (int j = 0; j < 4; j++) {
                float p = expf(s[i][j] * 0.125f - m_new);
                Ps[ty * 4 + i][tx * 4 + j] = p;
                rs += p;
            }
            rs = rsum16(rs);
            l_run[i] = l_run[i] * fac + rs;
            m_run[i] = m_new;
            #pragma unroll
            for (int j = 0; j < 4; j++) O[i][j] *= fac;
        }
        __syncthreads();

        #pragma unroll 8
        for (int t = 0; t < 64; t++) {
            float a[4], bv[4];
            #pragma unroll
            for (int i = 0; i < 4; i++) a[i]  = Ps[ty * 4 + i][t];
            #pragma unroll
            for (int j = 0; j < 4; j++) bv[j] = Vs[t][tx * 4 + j];
            #pragma unroll
            for (int i = 0; i < 4; i++)
                #pragma unroll
                for (int j = 0; j < 4; j++) O[i][j] += a[i] * bv[j];
        }
    }

    float ah = alpha[hh];
    #pragma unroll
    for (int i = 0; i < 4; i++) {
        float inv = 1.f / l_run[i];
        int row = qt * 64 + ty * 4 + i;
        #pragma unroll
        for (int j = 0; j < 4; j++) {
            long idx = (long)(b * SS + row) * DD + hh * 64 + tx * 4 + j;
            oq[idx] = __float2half(O[i][j] * inv + ah * h[idx]);
        }
    }
}

// ---------------- silu(g)*u -> fp16 (vectorized x4) ----------------
struct alignas(8) Hx4 { __half v[4]; };
__global__ void silumul_h(const float* __restrict__ gu, __half* __restrict__ ha) {
    long i = ((long)blockIdx.x * 256 + threadIdx.x) * 4;
    long m = i >> 12, j = i & 4095;
    float4 a4 = *(const float4*)(gu + (m << 13) + j);
    float4 u4 = *(const float4*)(gu + (m << 13) + 4096 + j);
    float av[4] = {a4.x, a4.y, a4.z, a4.w};
    float uv[4] = {u4.x, u4.y, u4.z, u4.w};
    Hx4 o;
    #pragma unroll
    for (int c = 0; c < 4; c++) {
        float val = av[c] / (1.f + expf(-av[c])) * uv[c];
        o.v[c] = __float2half(val);
    }
    *(Hx4*)(ha + i) = o;
}

// ---------------- host launcher ----------------
extern "C" void kernel_launch(void* const* d_in, const int* in_sizes, int n_in,
                              void* d_out, int out_size) {
    (void)in_sizes; (void)n_in; (void)out_size;
    const int*   ids   = (const int*)  d_in[0];
    const void*  emb_t = d_in[1];
    const float* emb_s = (const float*)d_in[2];
    const void*  qt = d_in[3];  const float* qs = (const float*)d_in[4];
    const void*  kt = d_in[5];  const float* ks = (const float*)d_in[6];
    const void*  vt = d_in[7];  const float* vs = (const float*)d_in[8];
    const void*  ot = d_in[9];  const float* os = (const float*)d_in[10];
    const void*  gt = d_in[11]; const float* gs = (const float*)d_in[12];
    const void*  ut = d_in[13]; const float* us = (const float*)d_in[14];
    const void*  dt = d_in[15]; const float* ds = (const float*)d_in[16];
    const float* wa    = (const float*)d_in[17];
    const float* wm    = (const float*)d_in[18];
    const float* alpha = (const float*)d_in[19];
    const float* wf    = (const float*)d_in[20];
    const void*  ht = d_in[21]; const float* hs = (const float*)d_in[22];
    float* out = (float*)d_out;

    float *x, *h, *qkv, *gu, *scb;
    __half *wh, *ha;
    cudaGetSymbolAddress((void**)&x,   g_x);
    cudaGetSymbolAddress((void**)&h,   g_h);
    cudaGetSymbolAddress((void**)&qkv, g_qkv);
    cudaGetSymbolAddress((void**)&gu,  g_gu);
    cudaGetSymbolAddress((void**)&wh,  g_wh);
    cudaGetSymbolAddress((void**)&scb, g_sc);
    cudaGetSymbolAddress((void**)&ha,  g_ha);

    cudaFuncSetAttribute(gemm1h<false>, cudaFuncAttributeMaxDynamicSharedMemorySize, GSM1);
    cudaFuncSetAttribute(gemm1h<true>,  cudaFuncAttributeMaxDynamicSharedMemorySize, GSM1);
    cudaFuncSetAttribute(attn_flash, cudaFuncAttributeMaxDynamicSharedMemorySize, 4 * 64 * 65 * 4);

    probe_kernel<<<1, 32>>>(emb_t);

    const long SZD = (long)DD * DD;       // 1,048,576
    const long SZF = (long)DFFN * DD;     // 4,194,304
    const long ngD = SZD / 128, ngF = SZF / 128;

    // batched weight converts (13 tensors, one launch)
    {
        CvtArgs ca;
        ScArgs  sa;
        int i = 0;
        auto add = [&](const void* wsrc, const float* ssrc, long so, long dofs, long n) {
            ca.src[i] = wsrc; ca.srcOff[i] = so; ca.dstOff[i] = dofs; ca.n[i] = n;
            sa.src[i] = ssrc; sa.srcOff[i] = so / 128; sa.dstOff[i] = dofs / 128; sa.n[i] = n / 128;
            i++;
        };
        for (int l = 0; l < LLAY; l++) {
            add(qt, qs, l * SZD, OQKV + (long)l * 3 * SZD,           SZD);
            add(kt, ks, l * SZD, OQKV + (long)l * 3 * SZD + SZD,     SZD);
            add(vt, vs, l * SZD, OQKV + (long)l * 3 * SZD + 2 * SZD, SZD);
            add(gt, gs, l * SZF, OGU  + (long)l * 2 * SZF,           SZF);
            add(ut, us, l * SZF, OGU  + (long)l * 2 * SZF + SZF,     SZF);
        }
        add(ot, os, 0, OO,  (long)LLAY * SZD);
        add(dt, ds, 0, ODW, (long)LLAY * SZF);
        add(ht, hs, 0, OHD, (long)VV * DD);
        convert_all<<<dim3(256, NCVT), 256>>>(ca);
        copy_sc_all<<<dim3(32, NCVT), 256>>>(sa);
    }

    embed_kernel<<<MM, 256>>>(ids, emb_t, emb_s, x);

    const size_t asmem = 4 * 64 * 65 * 4;

    for (int l = 0; l < LLAY; l++) {
        long oqkv = OQKV + (long)l * 3 * SZD;
        long oo   = OO   + (long)l * SZD;
        long ogu  = OGU  + (long)l * 2 * SZF;
        long odw  = ODW  + (long)l * SZF;

        rmsnorm_h<<<MM, 256>>>(x, wa + (long)l * DD, h, ha);
        gemm1h<false><<<dim3(24, 16), 512, GSM1>>>(ha, wh + oqkv, scb + oqkv / 128, qkv, MM, 3 * DD, DD);
        attn_flash<<<dim3(SS / 64, BB * HH), 256, asmem>>>(qkv, h, alpha + (long)l * HH, ha);
        gemm1h<true><<<dim3(8, 16), 512, GSM1>>>(ha, wh + oo, scb + oo / 128, x, MM, DD, DD);

        rmsnorm_h<<<MM, 256>>>(x, wm + (long)l * DD, nullptr, ha);
        gemm1h<false><<<dim3(64, 16), 512, GSM1>>>(ha, wh + ogu, scb + ogu / 128, gu, MM, 2 * DFFN, DD);
        silumul_h<<<(long)MM * DFFN / 1024, 256>>>(gu, ha);
        gemm1h<true><<<dim3(8, 16), 512, GSM1>>>(ha, wh + odw, scb + odw / 128, x, MM, DD, DFFN);
    }

    // final norm + head
    rmsnorm_h<<<MM, 256>>>(x, wf, nullptr, ha);
    gemm1h<false><<<dim3(VV / 128, 16), 512, GSM1>>>(ha, wh + OHD, scb + OHD / 128, out, MM, VV, DD);
}